// round 11
// baseline (speedup 1.0000x reference)
#include <cuda_runtime.h>
#include <cuda_bf16.h>
#include <math.h>
#include <stdint.h>

// Problem constants
#define N_SEQ  1024
#define B_SZ   4
#define C_DIM  1024
#define H_NUM  16
#define HD     64
#define BH     64          // B*H
#define M_ROWS 4096        // N*B
#define CW     512         // 32-bit words per C_DIM row of packed bf16
#define LOGMAX 4.6051701859880913680f  // log(100)
#define LOG2E  1.4426950408889634f

// Scratch (static device arrays -- no allocations allowed)
__device__ float g_qs[BH * N_SEQ * HD];  // fp32 [bh][n][d] (pre-norm q)
__device__ float g_ks[BH * N_SEQ * HD];

// Pre-split bf16 hi/lo packed words (2 bf16 per uint32)
__device__ uint32_t g_inh[3 * M_ROWS * CW];  // q,k,v inputs [z][m][w]
__device__ uint32_t g_inl[3 * M_ROWS * CW];
__device__ uint32_t g_wih[3 * 1024 * CW];    // in_proj_w
__device__ uint32_t g_wil[3 * 1024 * CW];
__device__ uint32_t g_woh[1024 * CW];        // out_w
__device__ uint32_t g_wol[1024 * CW];
__device__ uint32_t g_xh[M_ROWS * CW];       // attention output (N,B,C)
__device__ uint32_t g_xl[M_ROWS * CW];

// Attention operands
__device__ uint32_t g_qh[BH * N_SEQ * 32];   // normalized q/k [bh][n][dword]
__device__ uint32_t g_ql[BH * N_SEQ * 32];
__device__ uint32_t g_kh[BH * N_SEQ * 32];
__device__ uint32_t g_kl[BH * N_SEQ * 32];
__device__ __align__(16) __nv_bfloat16 g_vh16[BH * HD * N_SEQ];  // [bh][d][n] V^T hi
__device__ __align__(16) __nv_bfloat16 g_vl16[BH * HD * N_SEQ];  // lo

// ---------------------------------------------------------------------------
// Helpers (plain-target PTX only)
// ---------------------------------------------------------------------------
__device__ __forceinline__ uint32_t smem_u32(const void* p) {
    uint32_t a;
    asm("{ .reg .u64 t; cvta.to.shared.u64 t, %1; cvt.u32.u64 %0, t; }"
        : "=r"(a) : "l"(p));
    return a;
}

#define CP_ASYNC16(dst, src) \
    asm volatile("cp.async.cg.shared.global [%0], [%1], 16;" \
                 :: "r"(dst), "l"(src))
#define CP_COMMIT()  asm volatile("cp.async.commit_group;" ::: "memory")
#define CP_WAIT(n)   asm volatile("cp.async.wait_group %0;" :: "n"(n) : "memory")

__device__ __forceinline__ void ldsm_x4(uint32_t* r, uint32_t addr) {
    asm volatile("ldmatrix.sync.aligned.m8n8.x4.shared.b16 {%0,%1,%2,%3}, [%4];"
                 : "=r"(r[0]), "=r"(r[1]), "=r"(r[2]), "=r"(r[3]) : "r"(addr));
}

__device__ __forceinline__ void mma_bf16(float* d, const uint32_t* a,
                                         uint32_t b0, uint32_t b1) {
    asm volatile(
        "mma.sync.aligned.m16n8k16.row.col.f32.bf16.bf16.f32 "
        "{%0,%1,%2,%3}, {%4,%5,%6,%7}, {%8,%9}, {%0,%1,%2,%3};"
        : "+f"(d[0]), "+f"(d[1]), "+f"(d[2]), "+f"(d[3])
        : "r"(a[0]), "r"(a[1]), "r"(a[2]), "r"(a[3]), "r"(b0), "r"(b1));
}

__device__ __forceinline__ uint32_t pack_bf2(float x, float y) {
    uint16_t lx = __bfloat16_as_ushort(__float2bfloat16_rn(x));
    uint16_t ly = __bfloat16_as_ushort(__float2bfloat16_rn(y));
    return (uint32_t)lx | ((uint32_t)ly << 16);
}

__device__ __forceinline__ void split2(float x, float y, uint32_t& hw, uint32_t& lw) {
    float hx = __bfloat162float(__float2bfloat16_rn(x));
    float hy = __bfloat162float(__float2bfloat16_rn(y));
    hw = pack_bf2(hx, hy);
    lw = pack_bf2(x - hx, y - hy);
}

__device__ __forceinline__ float fast_exp2(float x) {
    float y;
    asm("ex2.approx.f32 %0, %1;" : "=f"(y) : "f"(x));
    return y;
}

// ---------------------------------------------------------------------------
// Kernel 0: split pre-pass. fp32 tensor -> packed bf16 hi/lo word arrays.
// which: 0/1/2 = q/k/v input, 3 = in_proj_w, 4 = out_w.
// ---------------------------------------------------------------------------
__global__ void __launch_bounds__(256) split_pass(const float4* __restrict__ src,
                                                  int which, int nf4)
{
    int i = blockIdx.x * blockDim.x + threadIdx.x;
    if (i >= nf4) return;
    float4 v = src[i];
    uint32_t h0, l0, h1, l1;
    split2(v.x, v.y, h0, l0);
    split2(v.z, v.w, h1, l1);
    uint32_t *dh, *dl;
    size_t off = 2 * (size_t)i;
    if (which < 3)      { dh = g_inh + (size_t)which * M_ROWS * CW;
                          dl = g_inl + (size_t)which * M_ROWS * CW; }
    else if (which == 3){ dh = g_wih; dl = g_wil; }
    else                { dh = g_woh; dl = g_wol; }
    dh[off] = h0; dh[off + 1] = h1;
    dl[off] = l0; dl[off + 1] = l1;
}

// ---------------------------------------------------------------------------
// Tensor-core GEMM, 3xBF16, cp.async 4-stage pipeline + ldmatrix fragments:
//   C[m][j] = sum_c A[m][c]*W[j][c] + bias[j]
// Tile 128x128, BK=16, 8 warps (2x4), 64x32 warp tiles.
// Smem rows: 8 data words + 4 pad (SW=12 -> 48B rows, 16B-aligned for
// cp.async; ldmatrix 8-row fetches hit banks {12r mod 32} = all-disjoint).
// mode 0: z picks q/k/v; scatter q/k fp32 head layout, v transposed bf16.
// mode 1: A = g_xh/g_xl, linear fp32 store to dlin.
// ---------------------------------------------------------------------------
#define SW      12
#define PLANE_W (128 * SW)               // 1536 words
#define STAGE_W (4 * PLANE_W)            // Ah, Al, Bh, Bl : 6144 words = 24 KB
#define NSTAGE  4
#define GEMM_SMEM_BYTES (NSTAGE * STAGE_W * 4)   // 98304 bytes

__global__ void __launch_bounds__(256, 2) gemm_tc(
    const float* __restrict__ bias, float* __restrict__ dlin, int mode)
{
    extern __shared__ uint32_t sg[];
    const uint32_t sbase = smem_u32(sg);

    const int z = blockIdx.z;
    const uint32_t* Agh = (mode == 1) ? g_xh : g_inh + (size_t)z * M_ROWS * CW;
    const uint32_t* Agl = (mode == 1) ? g_xl : g_inl + (size_t)z * M_ROWS * CW;
    const uint32_t* Bgh = (mode == 1) ? g_woh : g_wih + (size_t)z * 1024 * CW;
    const uint32_t* Bgl = (mode == 1) ? g_wol : g_wil + (size_t)z * 1024 * CW;
    const float* bp = bias + z * C_DIM;

    const int m0 = blockIdx.y * 128;
    const int n0 = blockIdx.x * 128;
    const int tid  = threadIdx.x;
    const int wid  = tid >> 5;
    const int lane = tid & 31;
    const int warp_m = wid >> 2;
    const int warp_n = wid & 3;

    // cp.async fill mapping: thread covers (row tid>>1, 16B half tid&1) in
    // each of the 4 planes. Row start = frow*48B (16B aligned), halves at
    // +0 / +16B.
    const int frow  = tid >> 1;
    const int fhalf = tid & 1;

#define ISSUE(kit) {                                                            \
        int _st = (kit) & (NSTAGE - 1);                                         \
        uint32_t _dst = sbase + (uint32_t)((_st * STAGE_W) + frow * SW + fhalf * 4) * 4; \
        size_t _ao = (size_t)(m0 + frow) * CW + (kit) * 8 + fhalf * 4;          \
        size_t _bo = (size_t)(n0 + frow) * CW + (kit) * 8 + fhalf * 4;          \
        CP_ASYNC16(_dst,                   Agh + _ao);                          \
        CP_ASYNC16(_dst + PLANE_W * 4,     Agl + _ao);                          \
        CP_ASYNC16(_dst + 2 * PLANE_W * 4, Bgh + _bo);                          \
        CP_ASYNC16(_dst + 3 * PLANE_W * 4, Bgl + _bo);                          \
        CP_COMMIT();                                                            \
    }

    // ldmatrix lane-address components
    const int arow_l = (lane & 7) + ((lane >> 3) & 1) * 8;   // quadrant rows
    const int awrd_l = (lane >> 4) * 4;                      // k-half words
    uint32_t aoff[4];
#pragma unroll
    for (int mt = 0; mt < 4; mt++)
        aoff[mt] = (uint32_t)(((warp_m * 64 + mt * 16 + arow_l) * SW + awrd_l) * 4);
    const int brow_l = warp_n * 32 + ((lane >> 4) * 8) + (lane & 7);
    const int bwrd_l = ((lane >> 3) & 1) * 4;
    uint32_t boff[2];
#pragma unroll
    for (int p = 0; p < 2; p++)
        boff[p] = (uint32_t)(((brow_l + p * 16) * SW + bwrd_l) * 4);

    float acc[4][4][4];
#pragma unroll
    for (int i = 0; i < 4; i++)
#pragma unroll
        for (int j = 0; j < 4; j++)
#pragma unroll
            for (int c = 0; c < 4; c++) acc[i][j][c] = 0.f;

    const int NIT = C_DIM / 16;   // 64

    ISSUE(0); ISSUE(1); ISSUE(2);

    for (int it = 0; it < NIT; it++) {
        // stage `it` complete after this wait (3 groups in flight steady-state)
        if (it <= NIT - 3)      CP_WAIT(2);
        else if (it == NIT - 2) CP_WAIT(1);
        else                    CP_WAIT(0);
        __syncthreads();
        if (it + 3 < NIT) ISSUE(it + 3);

        const uint32_t bAh = sbase + (uint32_t)((it & (NSTAGE - 1)) * STAGE_W) * 4;
        const uint32_t bAl = bAh + PLANE_W * 4;
        const uint32_t bBh = bAh + 2 * PLANE_W * 4;
        const uint32_t bBl = bAh + 3 * PLANE_W * 4;

        uint32_t bh[2][4], bl[2][4];
        ldsm_x4(bh[0], bBh + boff[0]);
        ldsm_x4(bh[1], bBh + boff[1]);
        ldsm_x4(bl[0], bBl + boff[0]);
        ldsm_x4(bl[1], bBl + boff[1]);

#pragma unroll
        for (int mt = 0; mt < 4; mt++) {
            uint32_t ah[4], al[4];
            ldsm_x4(ah, bAh + aoff[mt]);
            ldsm_x4(al, bAl + aoff[mt]);
#pragma unroll
            for (int n8 = 0; n8 < 4; n8++) {
                const int p = n8 >> 1, e = (n8 & 1) * 2;
                mma_bf16(acc[mt][n8], ah, bh[p][e], bh[p][e + 1]);  // hi*hi
                mma_bf16(acc[mt][n8], ah, bl[p][e], bl[p][e + 1]);  // hi*lo
                mma_bf16(acc[mt][n8], al, bh[p][e], bh[p][e + 1]);  // lo*hi
            }
        }
    }
#undef ISSUE

    // Epilogue. D frag: c0,c1 = (row lane>>2, cols 2(lane&3),+1); c2,c3 = row+8.
    const int erow = lane >> 2;
    const int ecol = (lane & 3) * 2;
#pragma unroll
    for (int mt = 0; mt < 4; mt++) {
#pragma unroll
        for (int nt = 0; nt < 4; nt++) {
            int col = n0 + warp_n * 32 + nt * 8 + ecol;
            float bx = bp[col], by = bp[col + 1];
#pragma unroll
            for (int half = 0; half < 2; half++) {
                int m = m0 + warp_m * 64 + mt * 16 + erow + half * 8;
                float v0 = acc[mt][nt][half * 2 + 0] + bx;
                float v1 = acc[mt][nt][half * 2 + 1] + by;
                if (mode == 0) {
                    int n = m >> 2, bb = m & 3;     // row m = n*B + b
                    int h = col >> 6, d = col & 63;
                    if (z == 2) {
                        size_t base = ((size_t)(bb * H_NUM + h) * HD + d) * N_SEQ + n;
                        float h0 = __bfloat162float(__float2bfloat16_rn(v0));
                        float h1 = __bfloat162float(__float2bfloat16_rn(v1));
                        g_vh16[base]         = __float2bfloat16_rn(v0);
                        g_vl16[base]         = __float2bfloat16_rn(v0 - h0);
                        g_vh16[base + N_SEQ] = __float2bfloat16_rn(v1);
                        g_vl16[base + N_SEQ] = __float2bfloat16_rn(v1 - h1);
                    } else {
                        float* outp = (z == 0) ? g_qs : g_ks;
                        float2 v = { v0, v1 };
                        *(float2*)(outp + (((size_t)(bb * H_NUM + h) * N_SEQ) + n) * HD + d) = v;
                    }
                } else {
                    float2 v = { v0, v1 };
                    *(float2*)(dlin + (size_t)m * C_DIM + col) = v;
                }
            }
        }
    }
}

// ---------------------------------------------------------------------------
// Kernel 2: L2-normalize q/k rows, fold exp(min(ls,log100))*log2e into q,
// emit packed bf16 hi/lo words. One warp per row.
// ---------------------------------------------------------------------------
__global__ void __launch_bounds__(256) norm_kernel(const float* __restrict__ logit_scale)
{
    int wrow = (blockIdx.x * blockDim.x + threadIdx.x) >> 5;
    int lane = threadIdx.x & 31;
    const int rows_per_tensor = BH * N_SEQ;  // 65536
    if (wrow >= 2 * rows_per_tensor) return;
    int which = wrow >= rows_per_tensor;
    int row = wrow - which * rows_per_tensor;   // = bh*N + n
    const float* ptr = (which ? g_ks : g_qs) + (size_t)row * HD;

    float x0 = ptr[2 * lane];
    float x1 = ptr[2 * lane + 1];
    float ss = x0 * x0 + x1 * x1;
#pragma unroll
    for (int o = 16; o > 0; o >>= 1) ss += __shfl_xor_sync(0xffffffffu, ss, o);
    float scale = 1.0f / fmaxf(sqrtf(ss), 1e-12f);
    if (!which) {
        int h = (row >> 10) & 15;
        scale *= expf(fminf(logit_scale[h], LOGMAX)) * LOG2E;  // base-2 softmax
    }
    uint32_t hw, lw;
    split2(x0 * scale, x1 * scale, hw, lw);
    uint32_t* dh = which ? g_kh : g_qh;
    uint32_t* dl = which ? g_kl : g_ql;
    dh[(size_t)row * 32 + lane] = hw;
    dl[(size_t)row * 32 + lane] = lw;
}

// ---------------------------------------------------------------------------
// Kernel 3: tensor-core flash attention. Block = 128 q x one head; 8 warps,
// each owns 16 complete query rows. Epilogue writes split bf16 g_x.
// ---------------------------------------------------------------------------
#define AW    36
#define Q_H   0
#define Q_L   (128 * AW)
#define K_H   (2 * 128 * AW)
#define K_L   (K_H + 64 * AW)
#define V_H   (K_L + 64 * AW)
#define V_L   (V_H + 64 * AW)
#define ATTN_SMEM_WORDS (V_L + 64 * AW)
#define ATTN_SMEM_BYTES (ATTN_SMEM_WORDS * 4)        // 73728 bytes

__global__ void __launch_bounds__(256, 2) attn_kernel()
{
    extern __shared__ uint32_t sa[];

    const int bh = blockIdx.y;
    const int n0 = blockIdx.x * 128;
    const int tid  = threadIdx.x;
    const int warp = tid >> 5;
    const int lane = tid & 31;
    const int g    = lane >> 2;
    const int tig  = lane & 3;
    const int qr   = warp * 16;

    const size_t qrow0 = (size_t)bh * N_SEQ + n0;
    const size_t krow0 = (size_t)bh * N_SEQ;
    const size_t vrow0 = (size_t)bh * HD;
    const uint32_t* vwh = (const uint32_t*)g_vh16;
    const uint32_t* vwl = (const uint32_t*)g_vl16;

#pragma unroll
    for (int u = 0; u < 4; u++) {
        int f = tid + 256 * u;
        int r = f >> 3, w4 = (f & 7) << 2;
        *(uint4*)&sa[Q_H + r * AW + w4] = *(const uint4*)&g_qh[(qrow0 + r) * 32 + w4];
        *(uint4*)&sa[Q_L + r * AW + w4] = *(const uint4*)&g_ql[(qrow0 + r) * 32 + w4];
    }

    float m0 = -1e30f, m1 = -1e30f, l0 = 0.f, l1 = 0.f;
    float o_acc[8][4];
#pragma unroll
    for (int i = 0; i < 8; i++)
#pragma unroll
        for (int c = 0; c < 4; c++) o_acc[i][c] = 0.f;

    for (int kt = 0; kt < N_SEQ / 64; kt++) {
        __syncthreads();
#pragma unroll
        for (int u = 0; u < 2; u++) {
            int f = tid + 256 * u;
            int r = f >> 3, w4 = (f & 7) << 2;
            *(uint4*)&sa[K_H + r * AW + w4] = *(const uint4*)&g_kh[(krow0 + kt * 64 + r) * 32 + w4];
            *(uint4*)&sa[K_L + r * AW + w4] = *(const uint4*)&g_kl[(krow0 + kt * 64 + r) * 32 + w4];
            *(uint4*)&sa[V_H + r * AW + w4] = *(const uint4*)&vwh[(vrow0 + r) * 512 + kt * 32 + w4];
            *(uint4*)&sa[V_L + r * AW + w4] = *(const uint4*)&vwl[(vrow0 + r) * 512 + kt * 32 + w4];
        }
        __syncthreads();

        // ---- S = Q K^T, 3xbf16 ----
        float s_acc[8][4];
#pragma unroll
        for (int i = 0; i < 8; i++)
#pragma unroll
            for (int c = 0; c < 4; c++) s_acc[i][c] = 0.f;

#pragma unroll
        for (int s = 0; s < 4; s++) {
            const int kw = s * 8 + tig;
            const int rb = (qr + g) * AW;
            uint32_t qh[4], ql[4];
            qh[0] = sa[Q_H + rb + kw];          qh[1] = sa[Q_H + rb + 8 * AW + kw];
            qh[2] = sa[Q_H + rb + kw + 4];      qh[3] = sa[Q_H + rb + 8 * AW + kw + 4];
            ql[0] = sa[Q_L + rb + kw];          ql[1] = sa[Q_L + rb + 8 * AW + kw];
            ql[2] = sa[Q_L + rb + kw + 4];      ql[3] = sa[Q_L + rb + 8 * AW + kw + 4];
#pragma unroll
            for (int nt = 0; nt < 8; nt++) {
                int kb = (nt * 8 + g) * AW;
                uint32_t kh0 = sa[K_H + kb + kw], kh1 = sa[K_H + kb + kw + 4];
                uint32_t kl0 = sa[K_L + kb + kw], kl1 = sa[K_L + kb + kw + 4];
                mma_bf16(s_acc[nt], qh, kh0, kh1);
                mma_bf16(s_acc[nt], qh, kl0, kl1);
                mma_bf16(s_acc[nt], ql, kh0, kh1);
            }
        }

        // ---- online softmax (base-2) ----
        float rmax0 = -1e30f, rmax1 = -1e30f;
#pragma unroll
        for (int nt = 0; nt < 8; nt++) {
            rmax0 = fmaxf(rmax0, fmaxf(s_acc[nt][0], s_acc[nt][1]));
            rmax1 = fmaxf(rmax1, fmaxf(s_acc[nt][2], s_acc[nt][3]));
        }
        rmax0 = fmaxf(rmax0, __shfl_xor_sync(0xffffffffu, rmax0, 1));
        rmax0 = fmaxf(rmax0, __shfl_xor_sync(0xffffffffu, rmax0, 2));
        rmax1 = fmaxf(rmax1, __shfl_xor_sync(0xffffffffu, rmax1, 1));
        rmax1 = fmaxf(rmax1, __shfl_xor_sync(0xffffffffu, rmax1, 2));
        float mn0 = fmaxf(m0, rmax0), mn1 = fmaxf(m1, rmax1);
        float corr0 = fast_exp2(m0 - mn0), corr1 = fast_exp2(m1 - mn1);
        float rs0 = 0.f, rs1 = 0.f;
#pragma unroll
        for (int nt = 0; nt < 8; nt++) {
            s_acc[nt][0] = fast_exp2(s_acc[nt][0] - mn0);
            s_acc[nt][1] = fast_exp2(s_acc[nt][1] - mn0);
            s_acc[nt][2] = fast_exp2(s_acc[nt][2] - mn1);
            s_acc[nt][3] = fast_exp2(s_acc[nt][3] - mn1);
            rs0 += s_acc[nt][0] + s_acc[nt][1];
            rs1 += s_acc[nt][2] + s_acc[nt][3];
        }
        rs0 += __shfl_xor_sync(0xffffffffu, rs0, 1);
        rs0 += __shfl_xor_sync(0xffffffffu, rs0, 2);
        rs1 += __shfl_xor_sync(0xffffffffu, rs1, 1);
        rs1 += __shfl_xor_sync(0xffffffffu, rs1, 2);
        l0 = l0 * corr0 + rs0;  m0 = mn0;
        l1 = l1 * corr1 + rs1;  m1 = mn1;
#pragma unroll
        for (int nt = 0; nt < 8; nt++) {
            o_acc[nt][0] *= corr0;  o_acc[nt][1] *= corr0;
            o_acc[nt][2] *= corr1;  o_acc[nt][3] *= corr1;
        }

        // ---- O += P V ----
#pragma unroll
        for (int s = 0; s < 4; s++) {
            uint32_t pah[4], pal[4];
            split2(s_acc[2 * s][0],     s_acc[2 * s][1],     pah[0], pal[0]);
            split2(s_acc[2 * s][2],     s_acc[2 * s][3],     pah[1], pal[1]);
            split2(s_acc[2 * s + 1][0], s_acc[2 * s + 1][1], pah[2], pal[2]);
            split2(s_acc[2 * s + 1][2], s_acc[2 * s + 1][3], pah[3], pal[3]);
            const int kw = s * 8 + tig;
#pragma unroll
            for (int nt = 0; nt < 8; nt++) {
                int vb = (nt * 8 + g) * AW;
                uint32_t vh0 = sa[V_H + vb + kw], vh1 = sa[V_H + vb + kw + 4];
                uint32_t vl0 = sa[V_L + vb + kw], vl1 = sa[V_L + vb + kw + 4];
                mma_bf16(o_acc[nt], pah, vh0, vh1);
                mma_bf16(o_acc[nt], pah, vl0, vl1);
                mma_bf16(o_acc[nt], pal, vh0, vh1);
            }
        }
    }

    // Epilogue: out[q][d] = o/l, stored pre-split for the output projection
    const int bb = bh >> 4;
    const int h  = bh & 15;
    float inv0 = 1.0f / l0, inv1 = 1.0f / l1;
    int nq0 = n0 + qr + g;
    size_t row0 = ((size_t)nq0 * B_SZ + bb) * CW;
    size_t row1 = ((size_t)(nq0 + 8) * B_SZ + bb) * CW;
#pragma unroll
    for (int nt = 0; nt < 8; nt++) {
        int w = h * 32 + nt * 4 + tig;
        uint32_t hw, lw;
        split2(o_acc[nt][0] * inv0, o_acc[nt][1] * inv0, hw, lw);
        g_xh[row0 + w] = hw;  g_xl[row0 + w] = lw;
        split2(o_acc[nt][2] * inv1, o_acc[nt][3] * inv1, hw, lw);
        g_xh[row1 + w] = hw;  g_xl[row1 + w] = lw;
    }
}

// ---------------------------------------------------------------------------
extern "C" void kernel_launch(void* const* d_in, const int* in_sizes, int n_in,
                              void* d_out, int out_size)
{
    const float* q     = (const float*)d_in[0];
    const float* k     = (const float*)d_in[1];
    const float* v     = (const float*)d_in[2];
    const float* w_in  = (const float*)d_in[3];
    const float* b_in  = (const float*)d_in[4];
    const float* ls    = (const float*)d_in[5];
    const float* w_out = (const float*)d_in[6];
    const float* b_out = (const float*)d_in[7];
    float* out = (float*)d_out;

    cudaFuncSetAttribute(gemm_tc,
                         cudaFuncAttributeMaxDynamicSharedMemorySize,
                         GEMM_SMEM_BYTES);
    cudaFuncSetAttribute(attn_kernel,
                         cudaFuncAttributeMaxDynamicSharedMemorySize,
                         ATTN_SMEM_BYTES);

    const int nf4_in = M_ROWS * C_DIM / 4;
    const int nf4_wi = 3 * 1024 * C_DIM / 4;
    const int nf4_wo = 1024 * C_DIM / 4;
    split_pass<<<nf4_in / 256, 256>>>((const float4*)q,     0, nf4_in);
    split_pass<<<nf4_in / 256, 256>>>((const float4*)k,     1, nf4_in);
    split_pass<<<nf4_in / 256, 256>>>((const float4*)v,     2, nf4_in);
    split_pass<<<nf4_wi / 256, 256>>>((const float4*)w_in,  3, nf4_wi);
    split_pass<<<nf4_wo / 256, 256>>>((const float4*)w_out, 4, nf4_wo);

    gemm_tc<<<dim3(C_DIM / 128, M_ROWS / 128, 3), 256, GEMM_SMEM_BYTES>>>(
        b_in, nullptr, 0);
    norm_kernel<<<(2 * BH * N_SEQ) / 8, 256>>>(ls);
    attn_kernel<<<dim3(N_SEQ / 128, BH), 256, ATTN_SMEM_BYTES>>>();
    gemm_tc<<<dim3(C_DIM / 128, M_ROWS / 128, 1), 256, GEMM_SMEM_BYTES>>>(
        b_out, out, 1);
}

// round 12
// speedup vs baseline: 1.5072x; 1.5072x over previous
#include <cuda_runtime.h>
#include <cuda_bf16.h>
#include <math.h>
#include <stdint.h>

// Problem constants
#define N_SEQ  1024
#define B_SZ   4
#define C_DIM  1024
#define H_NUM  16
#define HD     64
#define BH     64          // B*H
#define M_ROWS 4096        // N*B
#define CW     512         // 32-bit words per C_DIM row of packed bf16
#define LOGMAX 4.6051701859880913680f  // log(100)
#define LOG2E  1.4426950408889634f

// Scratch (static device arrays -- no allocations allowed)
__device__ float g_qs[BH * N_SEQ * HD];  // fp32 [bh][n][d] (pre-norm q)
__device__ float g_ks[BH * N_SEQ * HD];

// Pre-split bf16 hi/lo packed words (2 bf16 per uint32)
__device__ uint32_t g_inh[3 * M_ROWS * CW];  // q,k,v inputs [z][m][w]
__device__ uint32_t g_inl[3 * M_ROWS * CW];
__device__ uint32_t g_wih[3 * 1024 * CW];    // in_proj_w
__device__ uint32_t g_wil[3 * 1024 * CW];
__device__ uint32_t g_woh[1024 * CW];        // out_w
__device__ uint32_t g_wol[1024 * CW];
__device__ uint32_t g_xh[M_ROWS * CW];       // attention output (N,B,C)
__device__ uint32_t g_xl[M_ROWS * CW];

// Attention operands
__device__ uint32_t g_qh[BH * N_SEQ * 32];   // normalized q/k [bh][n][dword]
__device__ uint32_t g_ql[BH * N_SEQ * 32];
__device__ uint32_t g_kh[BH * N_SEQ * 32];
__device__ uint32_t g_kl[BH * N_SEQ * 32];
__device__ __align__(16) __nv_bfloat16 g_vh16[BH * HD * N_SEQ];  // [bh][d][n] V^T hi
__device__ __align__(16) __nv_bfloat16 g_vl16[BH * HD * N_SEQ];  // lo

// ---------------------------------------------------------------------------
// Helpers (plain-target PTX only)
// ---------------------------------------------------------------------------
__device__ __forceinline__ uint32_t smem_u32(const void* p) {
    uint32_t a;
    asm("{ .reg .u64 t; cvta.to.shared.u64 t, %1; cvt.u32.u64 %0, t; }"
        : "=r"(a) : "l"(p));
    return a;
}

__device__ __forceinline__ void ldsm_x4(uint32_t* r, uint32_t addr) {
    asm volatile("ldmatrix.sync.aligned.m8n8.x4.shared.b16 {%0,%1,%2,%3}, [%4];"
                 : "=r"(r[0]), "=r"(r[1]), "=r"(r[2]), "=r"(r[3]) : "r"(addr));
}

__device__ __forceinline__ void mma_bf16(float* d, const uint32_t* a,
                                         uint32_t b0, uint32_t b1) {
    asm volatile(
        "mma.sync.aligned.m16n8k16.row.col.f32.bf16.bf16.f32 "
        "{%0,%1,%2,%3}, {%4,%5,%6,%7}, {%8,%9}, {%0,%1,%2,%3};"
        : "+f"(d[0]), "+f"(d[1]), "+f"(d[2]), "+f"(d[3])
        : "r"(a[0]), "r"(a[1]), "r"(a[2]), "r"(a[3]), "r"(b0), "r"(b1));
}

__device__ __forceinline__ uint32_t pack_bf2(float x, float y) {
    uint16_t lx = __bfloat16_as_ushort(__float2bfloat16_rn(x));
    uint16_t ly = __bfloat16_as_ushort(__float2bfloat16_rn(y));
    return (uint32_t)lx | ((uint32_t)ly << 16);
}

__device__ __forceinline__ void split2(float x, float y, uint32_t& hw, uint32_t& lw) {
    float hx = __bfloat162float(__float2bfloat16_rn(x));
    float hy = __bfloat162float(__float2bfloat16_rn(y));
    hw = pack_bf2(hx, hy);
    lw = pack_bf2(x - hx, y - hy);
}

__device__ __forceinline__ float fast_exp2(float x) {
    float y;
    asm("ex2.approx.f32 %0, %1;" : "=f"(y) : "f"(x));
    return y;
}

// ---------------------------------------------------------------------------
// Kernel 0: split pre-pass. fp32 tensor -> packed bf16 hi/lo word arrays.
// which: 0/1/2 = q/k/v input, 3 = in_proj_w, 4 = out_w.
// ---------------------------------------------------------------------------
__global__ void __launch_bounds__(256) split_pass(const float4* __restrict__ src,
                                                  int which, int nf4)
{
    int i = blockIdx.x * blockDim.x + threadIdx.x;
    if (i >= nf4) return;
    float4 v = src[i];
    uint32_t h0, l0, h1, l1;
    split2(v.x, v.y, h0, l0);
    split2(v.z, v.w, h1, l1);
    uint32_t *dh, *dl;
    size_t off = 2 * (size_t)i;
    if (which < 3)      { dh = g_inh + (size_t)which * M_ROWS * CW;
                          dl = g_inl + (size_t)which * M_ROWS * CW; }
    else if (which == 3){ dh = g_wih; dl = g_wil; }
    else                { dh = g_woh; dl = g_wol; }
    dh[off] = h0; dh[off + 1] = h1;
    dl[off] = l0; dl[off + 1] = l1;
}

// ---------------------------------------------------------------------------
// Tensor-core GEMM, 3xBF16, pre-split operands, PROVEN R7 pipeline
// (BK=32, double buffer, register-prefetched LDG, single sync per iter),
// fragment loads via ldmatrix.x4 (SW=20 rows: 16B-aligned, conflict-free).
//   C[m][j] = sum_c A[m][c]*W[j][c] + bias[j]
// Tile 128x128, 8 warps (2x4), 64x32 warp tiles.
// mode 0: z picks q/k/v; scatter q/k fp32 head layout, v transposed bf16.
// mode 1: A = g_xh/g_xl, linear fp32 store to dlin.
// ---------------------------------------------------------------------------
#define SW      20
#define PLANE_W (128 * SW)
#define STAGE_W (4 * PLANE_W)            // Ah, Al, Bh, Bl
#define GEMM_SMEM_BYTES (2 * STAGE_W * 4)   // 81920 bytes

__global__ void __launch_bounds__(256, 2) gemm_tc(
    const float* __restrict__ bias, float* __restrict__ dlin, int mode)
{
    extern __shared__ uint32_t sg[];
    const uint32_t sb = smem_u32(sg);

    const int z = blockIdx.z;
    const uint32_t* Agh = (mode == 1) ? g_xh : g_inh + (size_t)z * M_ROWS * CW;
    const uint32_t* Agl = (mode == 1) ? g_xl : g_inl + (size_t)z * M_ROWS * CW;
    const uint32_t* Bgh = (mode == 1) ? g_woh : g_wih + (size_t)z * 1024 * CW;
    const uint32_t* Bgl = (mode == 1) ? g_wol : g_wil + (size_t)z * 1024 * CW;
    const float* bp = bias + z * C_DIM;

    const int m0 = blockIdx.y * 128;
    const int n0 = blockIdx.x * 128;
    const int tid  = threadIdx.x;
    const int wid  = tid >> 5;
    const int lane = tid & 31;
    const int warp_m = wid >> 2;
    const int warp_n = wid & 3;

    float acc[4][4][4];
#pragma unroll
    for (int i = 0; i < 4; i++)
#pragma unroll
        for (int j = 0; j < 4; j++)
#pragma unroll
            for (int c = 0; c < 4; c++) acc[i][j][c] = 0.f;

    // fill indices: thread covers rows fr, fr+64, one uint4 at word fc
    const int fr = tid >> 2;
    const int fc = (tid & 3) << 2;
    uint4 pah[2], pal[2], pbh[2], pbl[2];

#define LDG_TILE(kit) {                                                          \
        int _kw = (kit) * 16;                                                    \
        _Pragma("unroll")                                                        \
        for (int u = 0; u < 2; u++) {                                            \
            int r = fr + 64 * u;                                                 \
            size_t ao = (size_t)(m0 + r) * CW + _kw + fc;                        \
            size_t bo = (size_t)(n0 + r) * CW + _kw + fc;                        \
            pah[u] = *(const uint4*)&Agh[ao];  pal[u] = *(const uint4*)&Agl[ao]; \
            pbh[u] = *(const uint4*)&Bgh[bo];  pbl[u] = *(const uint4*)&Bgl[bo]; \
        }                                                                        \
    }

#define STS_TILE(s) {                                                            \
        uint32_t* Ah = sg + (s) * STAGE_W;                                       \
        uint32_t* Al = Ah + PLANE_W;                                             \
        uint32_t* Bh = Ah + 2 * PLANE_W;                                         \
        uint32_t* Bl = Ah + 3 * PLANE_W;                                         \
        _Pragma("unroll")                                                        \
        for (int u = 0; u < 2; u++) {                                            \
            int w = (fr + 64 * u) * SW + fc;                                     \
            *(uint4*)&Ah[w] = pah[u];  *(uint4*)&Al[w] = pal[u];                 \
            *(uint4*)&Bh[w] = pbh[u];  *(uint4*)&Bl[w] = pbl[u];                 \
        }                                                                        \
    }

    // ldmatrix per-lane byte offsets (within a plane).
    // A quadrants: lanes 0-7 rows+0..7 w0 | 8-15 rows+8 w0 | 16-23 rows w+4 |
    // 24-31 rows+8 w+4  -> regs (g,kw),(g+8,kw),(g,kw+4),(g+8,kw+4). Proven map.
    const int arow_l = (lane & 7) + ((lane >> 3) & 1) * 8;
    const int awrd_l = (lane >> 4) * 4;
    uint32_t aoff[4];
#pragma unroll
    for (int mt = 0; mt < 4; mt++)
        aoff[mt] = (uint32_t)(((warp_m * 64 + mt * 16 + arow_l) * SW + awrd_l) * 4);
    // B quadrants: lanes 0-7 rows+0..7 w0 | 8-15 rows w+4 | 16-23 rows+8 w0 |
    // 24-31 rows+8 w+4 -> regs (n0-7,k0),(n0-7,k8),(n8-15,k0),(n8-15,k8).
    const int brow_l = ((lane >> 4) * 8) + (lane & 7);
    const int bwrd_l = ((lane >> 3) & 1) * 4;
    uint32_t boff[2];
#pragma unroll
    for (int p = 0; p < 2; p++)
        boff[p] = (uint32_t)(((warp_n * 32 + p * 16 + brow_l) * SW + bwrd_l) * 4);

    const int NIT = C_DIM / 32;   // 32

    LDG_TILE(0);
    STS_TILE(0);
    __syncthreads();

    for (int it = 0; it < NIT; it++) {
        const int s = it & 1;
        const bool pf = (it + 1 < NIT);
        if (pf) LDG_TILE(it + 1);

        const uint32_t bAh = sb + (uint32_t)(s * STAGE_W) * 4;
        const uint32_t bAl = bAh + PLANE_W * 4;
        const uint32_t bBh = bAh + 2 * PLANE_W * 4;
        const uint32_t bBl = bAh + 3 * PLANE_W * 4;

#pragma unroll
        for (int ks = 0; ks < 2; ks++) {
            const uint32_t kb = (uint32_t)(ks * 32);   // 8 words

            uint32_t bh[2][4], bl[2][4];
            ldsm_x4(bh[0], bBh + boff[0] + kb);
            ldsm_x4(bh[1], bBh + boff[1] + kb);
            ldsm_x4(bl[0], bBl + boff[0] + kb);
            ldsm_x4(bl[1], bBl + boff[1] + kb);

#pragma unroll
            for (int mt = 0; mt < 4; mt++) {
                uint32_t ah[4], al[4];
                ldsm_x4(ah, bAh + aoff[mt] + kb);
                ldsm_x4(al, bAl + aoff[mt] + kb);
#pragma unroll
                for (int n8 = 0; n8 < 4; n8++) {
                    const int p = n8 >> 1, e = (n8 & 1) * 2;
                    mma_bf16(acc[mt][n8], ah, bh[p][e], bh[p][e + 1]);  // hi*hi
                    mma_bf16(acc[mt][n8], ah, bl[p][e], bl[p][e + 1]);  // hi*lo
                    mma_bf16(acc[mt][n8], al, bh[p][e], bh[p][e + 1]);  // lo*hi
                }
            }
        }
        if (pf) STS_TILE(s ^ 1);
        __syncthreads();
    }

    // Epilogue. D frag: c0,c1 = (row lane>>2, cols 2(lane&3),+1); c2,c3 = row+8.
    const int erow = lane >> 2;
    const int ecol = (lane & 3) * 2;
#pragma unroll
    for (int mt = 0; mt < 4; mt++) {
#pragma unroll
        for (int nt = 0; nt < 4; nt++) {
            int col = n0 + warp_n * 32 + nt * 8 + ecol;
            float bx = bp[col], by = bp[col + 1];
#pragma unroll
            for (int half = 0; half < 2; half++) {
                int m = m0 + warp_m * 64 + mt * 16 + erow + half * 8;
                float v0 = acc[mt][nt][half * 2 + 0] + bx;
                float v1 = acc[mt][nt][half * 2 + 1] + by;
                if (mode == 0) {
                    int n = m >> 2, bb = m & 3;     // row m = n*B + b
                    int h = col >> 6, d = col & 63;
                    if (z == 2) {
                        size_t base = ((size_t)(bb * H_NUM + h) * HD + d) * N_SEQ + n;
                        float h0 = __bfloat162float(__float2bfloat16_rn(v0));
                        float h1 = __bfloat162float(__float2bfloat16_rn(v1));
                        g_vh16[base]         = __float2bfloat16_rn(v0);
                        g_vl16[base]         = __float2bfloat16_rn(v0 - h0);
                        g_vh16[base + N_SEQ] = __float2bfloat16_rn(v1);
                        g_vl16[base + N_SEQ] = __float2bfloat16_rn(v1 - h1);
                    } else {
                        float* outp = (z == 0) ? g_qs : g_ks;
                        float2 v = { v0, v1 };
                        *(float2*)(outp + (((size_t)(bb * H_NUM + h) * N_SEQ) + n) * HD + d) = v;
                    }
                } else {
                    float2 v = { v0, v1 };
                    *(float2*)(dlin + (size_t)m * C_DIM + col) = v;
                }
            }
        }
    }
#undef LDG_TILE
#undef STS_TILE
}

// ---------------------------------------------------------------------------
// Kernel 2: L2-normalize q/k rows, fold exp(min(ls,log100))*log2e into q,
// emit packed bf16 hi/lo words. One warp per row.
// ---------------------------------------------------------------------------
__global__ void __launch_bounds__(256) norm_kernel(const float* __restrict__ logit_scale)
{
    int wrow = (blockIdx.x * blockDim.x + threadIdx.x) >> 5;
    int lane = threadIdx.x & 31;
    const int rows_per_tensor = BH * N_SEQ;  // 65536
    if (wrow >= 2 * rows_per_tensor) return;
    int which = wrow >= rows_per_tensor;
    int row = wrow - which * rows_per_tensor;   // = bh*N + n
    const float* ptr = (which ? g_ks : g_qs) + (size_t)row * HD;

    float x0 = ptr[2 * lane];
    float x1 = ptr[2 * lane + 1];
    float ss = x0 * x0 + x1 * x1;
#pragma unroll
    for (int o = 16; o > 0; o >>= 1) ss += __shfl_xor_sync(0xffffffffu, ss, o);
    float scale = 1.0f / fmaxf(sqrtf(ss), 1e-12f);
    if (!which) {
        int h = (row >> 10) & 15;
        scale *= expf(fminf(logit_scale[h], LOGMAX)) * LOG2E;  // base-2 softmax
    }
    uint32_t hw, lw;
    split2(x0 * scale, x1 * scale, hw, lw);
    uint32_t* dh = which ? g_kh : g_qh;
    uint32_t* dl = which ? g_kl : g_ql;
    dh[(size_t)row * 32 + lane] = hw;
    dl[(size_t)row * 32 + lane] = lw;
}

// ---------------------------------------------------------------------------
// Kernel 3: tensor-core flash attention. Block = 128 q x one head; 8 warps,
// each owns 16 complete query rows. Epilogue writes split bf16 g_x.
// ---------------------------------------------------------------------------
#define AW    36
#define Q_H   0
#define Q_L   (128 * AW)
#define K_H   (2 * 128 * AW)
#define K_L   (K_H + 64 * AW)
#define V_H   (K_L + 64 * AW)
#define V_L   (V_H + 64 * AW)
#define ATTN_SMEM_WORDS (V_L + 64 * AW)
#define ATTN_SMEM_BYTES (ATTN_SMEM_WORDS * 4)        // 73728 bytes

__global__ void __launch_bounds__(256, 2) attn_kernel()
{
    extern __shared__ uint32_t sa[];

    const int bh = blockIdx.y;
    const int n0 = blockIdx.x * 128;
    const int tid  = threadIdx.x;
    const int warp = tid >> 5;
    const int lane = tid & 31;
    const int g    = lane >> 2;
    const int tig  = lane & 3;
    const int qr   = warp * 16;

    const size_t qrow0 = (size_t)bh * N_SEQ + n0;
    const size_t krow0 = (size_t)bh * N_SEQ;
    const size_t vrow0 = (size_t)bh * HD;
    const uint32_t* vwh = (const uint32_t*)g_vh16;
    const uint32_t* vwl = (const uint32_t*)g_vl16;

#pragma unroll
    for (int u = 0; u < 4; u++) {
        int f = tid + 256 * u;
        int r = f >> 3, w4 = (f & 7) << 2;
        *(uint4*)&sa[Q_H + r * AW + w4] = *(const uint4*)&g_qh[(qrow0 + r) * 32 + w4];
        *(uint4*)&sa[Q_L + r * AW + w4] = *(const uint4*)&g_ql[(qrow0 + r) * 32 + w4];
    }

    float m0 = -1e30f, m1 = -1e30f, l0 = 0.f, l1 = 0.f;
    float o_acc[8][4];
#pragma unroll
    for (int i = 0; i < 8; i++)
#pragma unroll
        for (int c = 0; c < 4; c++) o_acc[i][c] = 0.f;

    for (int kt = 0; kt < N_SEQ / 64; kt++) {
        __syncthreads();
#pragma unroll
        for (int u = 0; u < 2; u++) {
            int f = tid + 256 * u;
            int r = f >> 3, w4 = (f & 7) << 2;
            *(uint4*)&sa[K_H + r * AW + w4] = *(const uint4*)&g_kh[(krow0 + kt * 64 + r) * 32 + w4];
            *(uint4*)&sa[K_L + r * AW + w4] = *(const uint4*)&g_kl[(krow0 + kt * 64 + r) * 32 + w4];
            *(uint4*)&sa[V_H + r * AW + w4] = *(const uint4*)&vwh[(vrow0 + r) * 512 + kt * 32 + w4];
            *(uint4*)&sa[V_L + r * AW + w4] = *(const uint4*)&vwl[(vrow0 + r) * 512 + kt * 32 + w4];
        }
        __syncthreads();

        // ---- S = Q K^T, 3xbf16 ----
        float s_acc[8][4];
#pragma unroll
        for (int i = 0; i < 8; i++)
#pragma unroll
            for (int c = 0; c < 4; c++) s_acc[i][c] = 0.f;

#pragma unroll
        for (int s = 0; s < 4; s++) {
            const int kw = s * 8 + tig;
            const int rb = (qr + g) * AW;
            uint32_t qh[4], ql[4];
            qh[0] = sa[Q_H + rb + kw];          qh[1] = sa[Q_H + rb + 8 * AW + kw];
            qh[2] = sa[Q_H + rb + kw + 4];      qh[3] = sa[Q_H + rb + 8 * AW + kw + 4];
            ql[0] = sa[Q_L + rb + kw];          ql[1] = sa[Q_L + rb + 8 * AW + kw];
            ql[2] = sa[Q_L + rb + kw + 4];      ql[3] = sa[Q_L + rb + 8 * AW + kw + 4];
#pragma unroll
            for (int nt = 0; nt < 8; nt++) {
                int kb = (nt * 8 + g) * AW;
                uint32_t kh0 = sa[K_H + kb + kw], kh1 = sa[K_H + kb + kw + 4];
                uint32_t kl0 = sa[K_L + kb + kw], kl1 = sa[K_L + kb + kw + 4];
                mma_bf16(s_acc[nt], qh, kh0, kh1);
                mma_bf16(s_acc[nt], qh, kl0, kl1);
                mma_bf16(s_acc[nt], ql, kh0, kh1);
            }
        }

        // ---- online softmax (base-2) ----
        float rmax0 = -1e30f, rmax1 = -1e30f;
#pragma unroll
        for (int nt = 0; nt < 8; nt++) {
            rmax0 = fmaxf(rmax0, fmaxf(s_acc[nt][0], s_acc[nt][1]));
            rmax1 = fmaxf(rmax1, fmaxf(s_acc[nt][2], s_acc[nt][3]));
        }
        rmax0 = fmaxf(rmax0, __shfl_xor_sync(0xffffffffu, rmax0, 1));
        rmax0 = fmaxf(rmax0, __shfl_xor_sync(0xffffffffu, rmax0, 2));
        rmax1 = fmaxf(rmax1, __shfl_xor_sync(0xffffffffu, rmax1, 1));
        rmax1 = fmaxf(rmax1, __shfl_xor_sync(0xffffffffu, rmax1, 2));
        float mn0 = fmaxf(m0, rmax0), mn1 = fmaxf(m1, rmax1);
        float corr0 = fast_exp2(m0 - mn0), corr1 = fast_exp2(m1 - mn1);
        float rs0 = 0.f, rs1 = 0.f;
#pragma unroll
        for (int nt = 0; nt < 8; nt++) {
            s_acc[nt][0] = fast_exp2(s_acc[nt][0] - mn0);
            s_acc[nt][1] = fast_exp2(s_acc[nt][1] - mn0);
            s_acc[nt][2] = fast_exp2(s_acc[nt][2] - mn1);
            s_acc[nt][3] = fast_exp2(s_acc[nt][3] - mn1);
            rs0 += s_acc[nt][0] + s_acc[nt][1];
            rs1 += s_acc[nt][2] + s_acc[nt][3];
        }
        rs0 += __shfl_xor_sync(0xffffffffu, rs0, 1);
        rs0 += __shfl_xor_sync(0xffffffffu, rs0, 2);
        rs1 += __shfl_xor_sync(0xffffffffu, rs1, 1);
        rs1 += __shfl_xor_sync(0xffffffffu, rs1, 2);
        l0 = l0 * corr0 + rs0;  m0 = mn0;
        l1 = l1 * corr1 + rs1;  m1 = mn1;
#pragma unroll
        for (int nt = 0; nt < 8; nt++) {
            o_acc[nt][0] *= corr0;  o_acc[nt][1] *= corr0;
            o_acc[nt][2] *= corr1;  o_acc[nt][3] *= corr1;
        }

        // ---- O += P V ----
#pragma unroll
        for (int s = 0; s < 4; s++) {
            uint32_t pah[4], pal[4];
            split2(s_acc[2 * s][0],     s_acc[2 * s][1],     pah[0], pal[0]);
            split2(s_acc[2 * s][2],     s_acc[2 * s][3],     pah[1], pal[1]);
            split2(s_acc[2 * s + 1][0], s_acc[2 * s + 1][1], pah[2], pal[2]);
            split2(s_acc[2 * s + 1][2], s_acc[2 * s + 1][3], pah[3], pal[3]);
            const int kw = s * 8 + tig;
#pragma unroll
            for (int nt = 0; nt < 8; nt++) {
                int vb = (nt * 8 + g) * AW;
                uint32_t vh0 = sa[V_H + vb + kw], vh1 = sa[V_H + vb + kw + 4];
                uint32_t vl0 = sa[V_L + vb + kw], vl1 = sa[V_L + vb + kw + 4];
                mma_bf16(o_acc[nt], pah, vh0, vh1);
                mma_bf16(o_acc[nt], pah, vl0, vl1);
                mma_bf16(o_acc[nt], pal, vh0, vh1);
            }
        }
    }

    // Epilogue: out[q][d] = o/l, stored pre-split for the output projection
    const int bb = bh >> 4;
    const int h  = bh & 15;
    float inv0 = 1.0f / l0, inv1 = 1.0f / l1;
    int nq0 = n0 + qr + g;
    size_t row0 = ((size_t)nq0 * B_SZ + bb) * CW;
    size_t row1 = ((size_t)(nq0 + 8) * B_SZ + bb) * CW;
#pragma unroll
    for (int nt = 0; nt < 8; nt++) {
        int w = h * 32 + nt * 4 + tig;
        uint32_t hw, lw;
        split2(o_acc[nt][0] * inv0, o_acc[nt][1] * inv0, hw, lw);
        g_xh[row0 + w] = hw;  g_xl[row0 + w] = lw;
        split2(o_acc[nt][2] * inv1, o_acc[nt][3] * inv1, hw, lw);
        g_xh[row1 + w] = hw;  g_xl[row1 + w] = lw;
    }
}

// ---------------------------------------------------------------------------
extern "C" void kernel_launch(void* const* d_in, const int* in_sizes, int n_in,
                              void* d_out, int out_size)
{
    const float* q     = (const float*)d_in[0];
    const float* k     = (const float*)d_in[1];
    const float* v     = (const float*)d_in[2];
    const float* w_in  = (const float*)d_in[3];
    const float* b_in  = (const float*)d_in[4];
    const float* ls    = (const float*)d_in[5];
    const float* w_out = (const float*)d_in[6];
    const float* b_out = (const float*)d_in[7];
    float* out = (float*)d_out;

    cudaFuncSetAttribute(gemm_tc,
                         cudaFuncAttributeMaxDynamicSharedMemorySize,
                         GEMM_SMEM_BYTES);
    cudaFuncSetAttribute(attn_kernel,
                         cudaFuncAttributeMaxDynamicSharedMemorySize,
                         ATTN_SMEM_BYTES);

    const int nf4_in = M_ROWS * C_DIM / 4;
    const int nf4_wi = 3 * 1024 * C_DIM / 4;
    const int nf4_wo = 1024 * C_DIM / 4;
    split_pass<<<nf4_in / 256, 256>>>((const float4*)q,     0, nf4_in);
    split_pass<<<nf4_in / 256, 256>>>((const float4*)k,     1, nf4_in);
    split_pass<<<nf4_in / 256, 256>>>((const float4*)v,     2, nf4_in);
    split_pass<<<nf4_wi / 256, 256>>>((const float4*)w_in,  3, nf4_wi);
    split_pass<<<nf4_wo / 256, 256>>>((const float4*)w_out, 4, nf4_wo);

    gemm_tc<<<dim3(C_DIM / 128, M_ROWS / 128, 3), 256, GEMM_SMEM_BYTES>>>(
        b_in, nullptr, 0);
    norm_kernel<<<(2 * BH * N_SEQ) / 8, 256>>>(ls);
    attn_kernel<<<dim3(N_SEQ / 128, BH), 256, ATTN_SMEM_BYTES>>>();
    gemm_tc<<<dim3(C_DIM / 128, M_ROWS / 128, 1), 256, GEMM_SMEM_BYTES>>>(
        b_out, out, 1);
}

// round 13
// speedup vs baseline: 1.6783x; 1.1135x over previous
#include <cuda_runtime.h>
#include <cuda_bf16.h>
#include <math.h>
#include <stdint.h>

// Problem constants
#define N_SEQ  1024
#define B_SZ   4
#define C_DIM  1024
#define H_NUM  16
#define HD     64
#define BH     64          // B*H
#define M_ROWS 4096        // N*B
#define CW     512         // 32-bit words per C_DIM row of packed bf16
#define LOGMAX 4.6051701859880913680f  // log(100)
#define LOG2E  1.4426950408889634f

// Scratch (static device arrays -- no allocations allowed)
__device__ float g_qs[BH * N_SEQ * HD];  // fp32 [bh][n][d] (pre-norm q)
__device__ float g_ks[BH * N_SEQ * HD];

// Pre-split bf16 hi/lo packed words (2 bf16 per uint32)
__device__ uint32_t g_inh[3 * M_ROWS * CW];  // q,k,v inputs [z][m][w]
__device__ uint32_t g_inl[3 * M_ROWS * CW];
__device__ uint32_t g_wih[3 * 1024 * CW];    // in_proj_w
__device__ uint32_t g_wil[3 * 1024 * CW];
__device__ uint32_t g_woh[1024 * CW];        // out_w
__device__ uint32_t g_wol[1024 * CW];
__device__ uint32_t g_xh[M_ROWS * CW];       // attention output (N,B,C)
__device__ uint32_t g_xl[M_ROWS * CW];

// Attention operands
__device__ uint32_t g_qh[BH * N_SEQ * 32];   // normalized q/k [bh][n][dword]
__device__ uint32_t g_ql[BH * N_SEQ * 32];
__device__ uint32_t g_kh[BH * N_SEQ * 32];
__device__ uint32_t g_kl[BH * N_SEQ * 32];
__device__ __align__(16) __nv_bfloat16 g_vh16[BH * HD * N_SEQ];  // [bh][d][n] V^T hi
__device__ __align__(16) __nv_bfloat16 g_vl16[BH * HD * N_SEQ];  // lo

// ---------------------------------------------------------------------------
// Helpers (plain-target PTX only)
// ---------------------------------------------------------------------------
__device__ __forceinline__ uint32_t smem_u32(const void* p) {
    uint32_t a;
    asm("{ .reg .u64 t; cvta.to.shared.u64 t, %1; cvt.u32.u64 %0, t; }"
        : "=r"(a) : "l"(p));
    return a;
}

#define CP_ASYNC16(dst, src) \
    asm volatile("cp.async.cg.shared.global [%0], [%1], 16;" \
                 :: "r"(dst), "l"(src))
#define CP_COMMIT()  asm volatile("cp.async.commit_group;" ::: "memory")
#define CP_WAIT0()   asm volatile("cp.async.wait_group 0;" ::: "memory")

__device__ __forceinline__ void ldsm_x4(uint32_t* r, uint32_t addr) {
    asm volatile("ldmatrix.sync.aligned.m8n8.x4.shared.b16 {%0,%1,%2,%3}, [%4];"
                 : "=r"(r[0]), "=r"(r[1]), "=r"(r[2]), "=r"(r[3]) : "r"(addr));
}

__device__ __forceinline__ void mma_bf16(float* d, const uint32_t* a,
                                         uint32_t b0, uint32_t b1) {
    asm volatile(
        "mma.sync.aligned.m16n8k16.row.col.f32.bf16.bf16.f32 "
        "{%0,%1,%2,%3}, {%4,%5,%6,%7}, {%8,%9}, {%0,%1,%2,%3};"
        : "+f"(d[0]), "+f"(d[1]), "+f"(d[2]), "+f"(d[3])
        : "r"(a[0]), "r"(a[1]), "r"(a[2]), "r"(a[3]), "r"(b0), "r"(b1));
}

__device__ __forceinline__ uint32_t pack_bf2(float x, float y) {
    uint16_t lx = __bfloat16_as_ushort(__float2bfloat16_rn(x));
    uint16_t ly = __bfloat16_as_ushort(__float2bfloat16_rn(y));
    return (uint32_t)lx | ((uint32_t)ly << 16);
}

__device__ __forceinline__ void split2(float x, float y, uint32_t& hw, uint32_t& lw) {
    float hx = __bfloat162float(__float2bfloat16_rn(x));
    float hy = __bfloat162float(__float2bfloat16_rn(y));
    hw = pack_bf2(hx, hy);
    lw = pack_bf2(x - hx, y - hy);
}

__device__ __forceinline__ float fast_exp2(float x) {
    float y;
    asm("ex2.approx.f32 %0, %1;" : "=f"(y) : "f"(x));
    return y;
}

// ---------------------------------------------------------------------------
// Kernel 0: split pre-pass. fp32 tensor -> packed bf16 hi/lo word arrays.
// which: 0/1/2 = q/k/v input, 3 = in_proj_w, 4 = out_w.
// ---------------------------------------------------------------------------
__global__ void __launch_bounds__(256) split_pass(const float4* __restrict__ src,
                                                  int which, int nf4)
{
    int i = blockIdx.x * blockDim.x + threadIdx.x;
    if (i >= nf4) return;
    float4 v = src[i];
    uint32_t h0, l0, h1, l1;
    split2(v.x, v.y, h0, l0);
    split2(v.z, v.w, h1, l1);
    uint32_t *dh, *dl;
    size_t off = 2 * (size_t)i;
    if (which < 3)      { dh = g_inh + (size_t)which * M_ROWS * CW;
                          dl = g_inl + (size_t)which * M_ROWS * CW; }
    else if (which == 3){ dh = g_wih; dl = g_wil; }
    else                { dh = g_woh; dl = g_wol; }
    dh[off] = h0; dh[off + 1] = h1;
    dl[off] = l0; dl[off + 1] = l1;
}

// ---------------------------------------------------------------------------
// Tensor-core GEMM, 3xBF16, pre-split operands.
// PROVEN R12 structure (BK=32, 2-stage double buffer, single sync/iter,
// ldmatrix fragments, SW=20 conflict-free rows) with two deltas:
//  1. cp.async fill (SW=20 rows are 80B = 16B-aligned -> legal), issued
//     right after the barrier so the copy overlaps the whole MMA body.
//  2. Term-major MMA ordering: 16 independent MMAs between successive
//     accumulations into the same D registers (breaks HMMA RAW chains).
//   C[m][j] = sum_c A[m][c]*W[j][c] + bias[j]
// Tile 128x128, 8 warps (2x4), 64x32 warp tiles.
// mode 0: z picks q/k/v; scatter q/k fp32 head layout, v transposed bf16.
// mode 1: A = g_xh/g_xl, linear fp32 store to dlin.
// ---------------------------------------------------------------------------
#define SW      20
#define PLANE_W (128 * SW)
#define STAGE_W (4 * PLANE_W)            // Ah, Al, Bh, Bl
#define GEMM_SMEM_BYTES (2 * STAGE_W * 4)   // 81920 bytes

__global__ void __launch_bounds__(256, 2) gemm_tc(
    const float* __restrict__ bias, float* __restrict__ dlin, int mode)
{
    extern __shared__ uint32_t sg[];
    const uint32_t sb = smem_u32(sg);

    const int z = blockIdx.z;
    const uint32_t* Agh = (mode == 1) ? g_xh : g_inh + (size_t)z * M_ROWS * CW;
    const uint32_t* Agl = (mode == 1) ? g_xl : g_inl + (size_t)z * M_ROWS * CW;
    const uint32_t* Bgh = (mode == 1) ? g_woh : g_wih + (size_t)z * 1024 * CW;
    const uint32_t* Bgl = (mode == 1) ? g_wol : g_wil + (size_t)z * 1024 * CW;
    const float* bp = bias + z * C_DIM;

    const int m0 = blockIdx.y * 128;
    const int n0 = blockIdx.x * 128;
    const int tid  = threadIdx.x;
    const int wid  = tid >> 5;
    const int lane = tid & 31;
    const int warp_m = wid >> 2;
    const int warp_n = wid & 3;

    float acc[4][4][4];
#pragma unroll
    for (int i = 0; i < 4; i++)
#pragma unroll
        for (int j = 0; j < 4; j++)
#pragma unroll
            for (int c = 0; c < 4; c++) acc[i][j][c] = 0.f;

    // cp.async fill: thread covers rows fr, fr+64, one 16B chunk at word fc
    const int fr = tid >> 2;
    const int fc = (tid & 3) << 2;

#define ISSUE(kit) {                                                            \
        int _s = (kit) & 1;                                                     \
        int _kw = (kit) * 16;                                                   \
        _Pragma("unroll")                                                       \
        for (int u = 0; u < 2; u++) {                                           \
            int r = fr + 64 * u;                                                \
            uint32_t dst = sb + (uint32_t)(_s * STAGE_W + r * SW + fc) * 4;     \
            size_t ao = (size_t)(m0 + r) * CW + _kw + fc;                       \
            size_t bo = (size_t)(n0 + r) * CW + _kw + fc;                       \
            CP_ASYNC16(dst,                   Agh + ao);                        \
            CP_ASYNC16(dst + PLANE_W * 4,     Agl + ao);                        \
            CP_ASYNC16(dst + 2 * PLANE_W * 4, Bgh + bo);                        \
            CP_ASYNC16(dst + 3 * PLANE_W * 4, Bgl + bo);                        \
        }                                                                       \
        CP_COMMIT();                                                            \
    }

    // ldmatrix per-lane byte offsets (within a plane) -- proven R12 maps.
    const int arow_l = (lane & 7) + ((lane >> 3) & 1) * 8;
    const int awrd_l = (lane >> 4) * 4;
    uint32_t aoff[4];
#pragma unroll
    for (int mt = 0; mt < 4; mt++)
        aoff[mt] = (uint32_t)(((warp_m * 64 + mt * 16 + arow_l) * SW + awrd_l) * 4);
    const int brow_l = ((lane >> 4) * 8) + (lane & 7);
    const int bwrd_l = ((lane >> 3) & 1) * 4;
    uint32_t boff[2];
#pragma unroll
    for (int p = 0; p < 2; p++)
        boff[p] = (uint32_t)(((warp_n * 32 + p * 16 + brow_l) * SW + bwrd_l) * 4);

    const int NIT = C_DIM / 32;   // 32

    ISSUE(0);

    for (int it = 0; it < NIT; it++) {
        CP_WAIT0();            // stage `it` copy complete (this thread)
        __syncthreads();       // visible to all; prior reads of next buf done
        if (it + 1 < NIT) ISSUE(it + 1);   // overlaps the MMA body below

        const int s = it & 1;
        const uint32_t bAh = sb + (uint32_t)(s * STAGE_W) * 4;
        const uint32_t bAl = bAh + PLANE_W * 4;
        const uint32_t bBh = bAh + 2 * PLANE_W * 4;
        const uint32_t bBl = bAh + 3 * PLANE_W * 4;

#pragma unroll
        for (int ks = 0; ks < 2; ks++) {
            const uint32_t kb = (uint32_t)(ks * 32);   // 8 words

            uint32_t bh[2][4], bl[2][4];
            ldsm_x4(bh[0], bBh + boff[0] + kb);
            ldsm_x4(bh[1], bBh + boff[1] + kb);
            ldsm_x4(bl[0], bBl + boff[0] + kb);
            ldsm_x4(bl[1], bBl + boff[1] + kb);

            uint32_t ah[4][4], al[4][4];
#pragma unroll
            for (int mt = 0; mt < 4; mt++) {
                ldsm_x4(ah[mt], bAh + aoff[mt] + kb);
                ldsm_x4(al[mt], bAl + aoff[mt] + kb);
            }

            // Term-major: hh for all 16 tiles, then hl, then lh.
            // Per-accumulator order unchanged (hh,hl,lh) -> bit-identical.
#pragma unroll
            for (int mt = 0; mt < 4; mt++)
#pragma unroll
                for (int n8 = 0; n8 < 4; n8++) {
                    const int p = n8 >> 1, e = (n8 & 1) * 2;
                    mma_bf16(acc[mt][n8], ah[mt], bh[p][e], bh[p][e + 1]);
                }
#pragma unroll
            for (int mt = 0; mt < 4; mt++)
#pragma unroll
                for (int n8 = 0; n8 < 4; n8++) {
                    const int p = n8 >> 1, e = (n8 & 1) * 2;
                    mma_bf16(acc[mt][n8], ah[mt], bl[p][e], bl[p][e + 1]);
                }
#pragma unroll
            for (int mt = 0; mt < 4; mt++)
#pragma unroll
                for (int n8 = 0; n8 < 4; n8++) {
                    const int p = n8 >> 1, e = (n8 & 1) * 2;
                    mma_bf16(acc[mt][n8], al[mt], bh[p][e], bh[p][e + 1]);
                }
        }
    }
#undef ISSUE

    // Epilogue. D frag: c0,c1 = (row lane>>2, cols 2(lane&3),+1); c2,c3 = row+8.
    const int erow = lane >> 2;
    const int ecol = (lane & 3) * 2;
#pragma unroll
    for (int mt = 0; mt < 4; mt++) {
#pragma unroll
        for (int nt = 0; nt < 4; nt++) {
            int col = n0 + warp_n * 32 + nt * 8 + ecol;
            float bx = bp[col], by = bp[col + 1];
#pragma unroll
            for (int half = 0; half < 2; half++) {
                int m = m0 + warp_m * 64 + mt * 16 + erow + half * 8;
                float v0 = acc[mt][nt][half * 2 + 0] + bx;
                float v1 = acc[mt][nt][half * 2 + 1] + by;
                if (mode == 0) {
                    int n = m >> 2, bb = m & 3;     // row m = n*B + b
                    int h = col >> 6, d = col & 63;
                    if (z == 2) {
                        size_t base = ((size_t)(bb * H_NUM + h) * HD + d) * N_SEQ + n;
                        float h0 = __bfloat162float(__float2bfloat16_rn(v0));
                        float h1 = __bfloat162float(__float2bfloat16_rn(v1));
                        g_vh16[base]         = __float2bfloat16_rn(v0);
                        g_vl16[base]         = __float2bfloat16_rn(v0 - h0);
                        g_vh16[base + N_SEQ] = __float2bfloat16_rn(v1);
                        g_vl16[base + N_SEQ] = __float2bfloat16_rn(v1 - h1);
                    } else {
                        float* outp = (z == 0) ? g_qs : g_ks;
                        float2 v = { v0, v1 };
                        *(float2*)(outp + (((size_t)(bb * H_NUM + h) * N_SEQ) + n) * HD + d) = v;
                    }
                } else {
                    float2 v = { v0, v1 };
                    *(float2*)(dlin + (size_t)m * C_DIM + col) = v;
                }
            }
        }
    }
}

// ---------------------------------------------------------------------------
// Kernel 2: L2-normalize q/k rows, fold exp(min(ls,log100))*log2e into q,
// emit packed bf16 hi/lo words. One warp per row.
// ---------------------------------------------------------------------------
__global__ void __launch_bounds__(256) norm_kernel(const float* __restrict__ logit_scale)
{
    int wrow = (blockIdx.x * blockDim.x + threadIdx.x) >> 5;
    int lane = threadIdx.x & 31;
    const int rows_per_tensor = BH * N_SEQ;  // 65536
    if (wrow >= 2 * rows_per_tensor) return;
    int which = wrow >= rows_per_tensor;
    int row = wrow - which * rows_per_tensor;   // = bh*N + n
    const float* ptr = (which ? g_ks : g_qs) + (size_t)row * HD;

    float x0 = ptr[2 * lane];
    float x1 = ptr[2 * lane + 1];
    float ss = x0 * x0 + x1 * x1;
#pragma unroll
    for (int o = 16; o > 0; o >>= 1) ss += __shfl_xor_sync(0xffffffffu, ss, o);
    float scale = 1.0f / fmaxf(sqrtf(ss), 1e-12f);
    if (!which) {
        int h = (row >> 10) & 15;
        scale *= expf(fminf(logit_scale[h], LOGMAX)) * LOG2E;  // base-2 softmax
    }
    uint32_t hw, lw;
    split2(x0 * scale, x1 * scale, hw, lw);
    uint32_t* dh = which ? g_kh : g_qh;
    uint32_t* dl = which ? g_kl : g_ql;
    dh[(size_t)row * 32 + lane] = hw;
    dl[(size_t)row * 32 + lane] = lw;
}

// ---------------------------------------------------------------------------
// Kernel 3: tensor-core flash attention. Block = 128 q x one head; 8 warps,
// each owns 16 complete query rows. Epilogue writes split bf16 g_x.
// ---------------------------------------------------------------------------
#define AW    36
#define Q_H   0
#define Q_L   (128 * AW)
#define K_H   (2 * 128 * AW)
#define K_L   (K_H + 64 * AW)
#define V_H   (K_L + 64 * AW)
#define V_L   (V_H + 64 * AW)
#define ATTN_SMEM_WORDS (V_L + 64 * AW)
#define ATTN_SMEM_BYTES (ATTN_SMEM_WORDS * 4)        // 73728 bytes

__global__ void __launch_bounds__(256, 2) attn_kernel()
{
    extern __shared__ uint32_t sa[];

    const int bh = blockIdx.y;
    const int n0 = blockIdx.x * 128;
    const int tid  = threadIdx.x;
    const int warp = tid >> 5;
    const int lane = tid & 31;
    const int g    = lane >> 2;
    const int tig  = lane & 3;
    const int qr   = warp * 16;

    const size_t qrow0 = (size_t)bh * N_SEQ + n0;
    const size_t krow0 = (size_t)bh * N_SEQ;
    const size_t vrow0 = (size_t)bh * HD;
    const uint32_t* vwh = (const uint32_t*)g_vh16;
    const uint32_t* vwl = (const uint32_t*)g_vl16;

#pragma unroll
    for (int u = 0; u < 4; u++) {
        int f = tid + 256 * u;
        int r = f >> 3, w4 = (f & 7) << 2;
        *(uint4*)&sa[Q_H + r * AW + w4] = *(const uint4*)&g_qh[(qrow0 + r) * 32 + w4];
        *(uint4*)&sa[Q_L + r * AW + w4] = *(const uint4*)&g_ql[(qrow0 + r) * 32 + w4];
    }

    float m0 = -1e30f, m1 = -1e30f, l0 = 0.f, l1 = 0.f;
    float o_acc[8][4];
#pragma unroll
    for (int i = 0; i < 8; i++)
#pragma unroll
        for (int c = 0; c < 4; c++) o_acc[i][c] = 0.f;

    for (int kt = 0; kt < N_SEQ / 64; kt++) {
        __syncthreads();
#pragma unroll
        for (int u = 0; u < 2; u++) {
            int f = tid + 256 * u;
            int r = f >> 3, w4 = (f & 7) << 2;
            *(uint4*)&sa[K_H + r * AW + w4] = *(const uint4*)&g_kh[(krow0 + kt * 64 + r) * 32 + w4];
            *(uint4*)&sa[K_L + r * AW + w4] = *(const uint4*)&g_kl[(krow0 + kt * 64 + r) * 32 + w4];
            *(uint4*)&sa[V_H + r * AW + w4] = *(const uint4*)&vwh[(vrow0 + r) * 512 + kt * 32 + w4];
            *(uint4*)&sa[V_L + r * AW + w4] = *(const uint4*)&vwl[(vrow0 + r) * 512 + kt * 32 + w4];
        }
        __syncthreads();

        // ---- S = Q K^T, 3xbf16 ----
        float s_acc[8][4];
#pragma unroll
        for (int i = 0; i < 8; i++)
#pragma unroll
            for (int c = 0; c < 4; c++) s_acc[i][c] = 0.f;

#pragma unroll
        for (int s = 0; s < 4; s++) {
            const int kw = s * 8 + tig;
            const int rb = (qr + g) * AW;
            uint32_t qh[4], ql[4];
            qh[0] = sa[Q_H + rb + kw];          qh[1] = sa[Q_H + rb + 8 * AW + kw];
            qh[2] = sa[Q_H + rb + kw + 4];      qh[3] = sa[Q_H + rb + 8 * AW + kw + 4];
            ql[0] = sa[Q_L + rb + kw];          ql[1] = sa[Q_L + rb + 8 * AW + kw];
            ql[2] = sa[Q_L + rb + kw + 4];      ql[3] = sa[Q_L + rb + 8 * AW + kw + 4];
#pragma unroll
            for (int nt = 0; nt < 8; nt++) {
                int kb = (nt * 8 + g) * AW;
                uint32_t kh0 = sa[K_H + kb + kw], kh1 = sa[K_H + kb + kw + 4];
                uint32_t kl0 = sa[K_L + kb + kw], kl1 = sa[K_L + kb + kw + 4];
                mma_bf16(s_acc[nt], qh, kh0, kh1);
                mma_bf16(s_acc[nt], qh, kl0, kl1);
                mma_bf16(s_acc[nt], ql, kh0, kh1);
            }
        }

        // ---- online softmax (base-2) ----
        float rmax0 = -1e30f, rmax1 = -1e30f;
#pragma unroll
        for (int nt = 0; nt < 8; nt++) {
            rmax0 = fmaxf(rmax0, fmaxf(s_acc[nt][0], s_acc[nt][1]));
            rmax1 = fmaxf(rmax1, fmaxf(s_acc[nt][2], s_acc[nt][3]));
        }
        rmax0 = fmaxf(rmax0, __shfl_xor_sync(0xffffffffu, rmax0, 1));
        rmax0 = fmaxf(rmax0, __shfl_xor_sync(0xffffffffu, rmax0, 2));
        rmax1 = fmaxf(rmax1, __shfl_xor_sync(0xffffffffu, rmax1, 1));
        rmax1 = fmaxf(rmax1, __shfl_xor_sync(0xffffffffu, rmax1, 2));
        float mn0 = fmaxf(m0, rmax0), mn1 = fmaxf(m1, rmax1);
        float corr0 = fast_exp2(m0 - mn0), corr1 = fast_exp2(m1 - mn1);
        float rs0 = 0.f, rs1 = 0.f;
#pragma unroll
        for (int nt = 0; nt < 8; nt++) {
            s_acc[nt][0] = fast_exp2(s_acc[nt][0] - mn0);
            s_acc[nt][1] = fast_exp2(s_acc[nt][1] - mn0);
            s_acc[nt][2] = fast_exp2(s_acc[nt][2] - mn1);
            s_acc[nt][3] = fast_exp2(s_acc[nt][3] - mn1);
            rs0 += s_acc[nt][0] + s_acc[nt][1];
            rs1 += s_acc[nt][2] + s_acc[nt][3];
        }
        rs0 += __shfl_xor_sync(0xffffffffu, rs0, 1);
        rs0 += __shfl_xor_sync(0xffffffffu, rs0, 2);
        rs1 += __shfl_xor_sync(0xffffffffu, rs1, 1);
        rs1 += __shfl_xor_sync(0xffffffffu, rs1, 2);
        l0 = l0 * corr0 + rs0;  m0 = mn0;
        l1 = l1 * corr1 + rs1;  m1 = mn1;
#pragma unroll
        for (int nt = 0; nt < 8; nt++) {
            o_acc[nt][0] *= corr0;  o_acc[nt][1] *= corr0;
            o_acc[nt][2] *= corr1;  o_acc[nt][3] *= corr1;
        }

        // ---- O += P V ----
#pragma unroll
        for (int s = 0; s < 4; s++) {
            uint32_t pah[4], pal[4];
            split2(s_acc[2 * s][0],     s_acc[2 * s][1],     pah[0], pal[0]);
            split2(s_acc[2 * s][2],     s_acc[2 * s][3],     pah[1], pal[1]);
            split2(s_acc[2 * s + 1][0], s_acc[2 * s + 1][1], pah[2], pal[2]);
            split2(s_acc[2 * s + 1][2], s_acc[2 * s + 1][3], pah[3], pal[3]);
            const int kw = s * 8 + tig;
#pragma unroll
            for (int nt = 0; nt < 8; nt++) {
                int vb = (nt * 8 + g) * AW;
                uint32_t vh0 = sa[V_H + vb + kw], vh1 = sa[V_H + vb + kw + 4];
                uint32_t vl0 = sa[V_L + vb + kw], vl1 = sa[V_L + vb + kw + 4];
                mma_bf16(o_acc[nt], pah, vh0, vh1);
                mma_bf16(o_acc[nt], pah, vl0, vl1);
                mma_bf16(o_acc[nt], pal, vh0, vh1);
            }
        }
    }

    // Epilogue: out[q][d] = o/l, stored pre-split for the output projection
    const int bb = bh >> 4;
    const int h  = bh & 15;
    float inv0 = 1.0f / l0, inv1 = 1.0f / l1;
    int nq0 = n0 + qr + g;
    size_t row0 = ((size_t)nq0 * B_SZ + bb) * CW;
    size_t row1 = ((size_t)(nq0 + 8) * B_SZ + bb) * CW;
#pragma unroll
    for (int nt = 0; nt < 8; nt++) {
        int w = h * 32 + nt * 4 + tig;
        uint32_t hw, lw;
        split2(o_acc[nt][0] * inv0, o_acc[nt][1] * inv0, hw, lw);
        g_xh[row0 + w] = hw;  g_xl[row0 + w] = lw;
        split2(o_acc[nt][2] * inv1, o_acc[nt][3] * inv1, hw, lw);
        g_xh[row1 + w] = hw;  g_xl[row1 + w] = lw;
    }
}

// ---------------------------------------------------------------------------
extern "C" void kernel_launch(void* const* d_in, const int* in_sizes, int n_in,
                              void* d_out, int out_size)
{
    const float* q     = (const float*)d_in[0];
    const float* k     = (const float*)d_in[1];
    const float* v     = (const float*)d_in[2];
    const float* w_in  = (const float*)d_in[3];
    const float* b_in  = (const float*)d_in[4];
    const float* ls    = (const float*)d_in[5];
    const float* w_out = (const float*)d_in[6];
    const float* b_out = (const float*)d_in[7];
    float* out = (float*)d_out;

    cudaFuncSetAttribute(gemm_tc,
                         cudaFuncAttributeMaxDynamicSharedMemorySize,
                         GEMM_SMEM_BYTES);
    cudaFuncSetAttribute(attn_kernel,
                         cudaFuncAttributeMaxDynamicSharedMemorySize,
                         ATTN_SMEM_BYTES);

    const int nf4_in = M_ROWS * C_DIM / 4;
    const int nf4_wi = 3 * 1024 * C_DIM / 4;
    const int nf4_wo = 1024 * C_DIM / 4;
    split_pass<<<nf4_in / 256, 256>>>((const float4*)q,     0, nf4_in);
    split_pass<<<nf4_in / 256, 256>>>((const float4*)k,     1, nf4_in);
    split_pass<<<nf4_in / 256, 256>>>((const float4*)v,     2, nf4_in);
    split_pass<<<nf4_wi / 256, 256>>>((const float4*)w_in,  3, nf4_wi);
    split_pass<<<nf4_wo / 256, 256>>>((const float4*)w_out, 4, nf4_wo);

    gemm_tc<<<dim3(C_DIM / 128, M_ROWS / 128, 3), 256, GEMM_SMEM_BYTES>>>(
        b_in, nullptr, 0);
    norm_kernel<<<(2 * BH * N_SEQ) / 8, 256>>>(ls);
    attn_kernel<<<dim3(N_SEQ / 128, BH), 256, ATTN_SMEM_BYTES>>>();
    gemm_tc<<<dim3(C_DIM / 128, M_ROWS / 128, 1), 256, GEMM_SMEM_BYTES>>>(
        b_out, out, 1);
}

// round 14
// speedup vs baseline: 1.7150x; 1.0219x over previous
#include <cuda_runtime.h>
#include <cuda_bf16.h>
#include <math.h>
#include <stdint.h>

// Problem constants
#define N_SEQ  1024
#define B_SZ   4
#define C_DIM  1024
#define H_NUM  16
#define HD     64
#define BH     64          // B*H
#define M_ROWS 4096        // N*B
#define CW     512         // 32-bit words per C_DIM row of packed bf16
#define LOGMAX 4.6051701859880913680f  // log(100)
#define LOG2E  1.4426950408889634f

// Scratch (static device arrays -- no allocations allowed)
__device__ float g_qs[BH * N_SEQ * HD];  // fp32 [bh][n][d] (pre-norm q)
__device__ float g_ks[BH * N_SEQ * HD];

// Pre-split bf16 hi/lo packed words (2 bf16 per uint32)
__device__ __align__(16) uint32_t g_inh[3 * M_ROWS * CW];  // q,k,v inputs
__device__ __align__(16) uint32_t g_inl[3 * M_ROWS * CW];
__device__ __align__(16) uint32_t g_wih[3 * 1024 * CW];    // in_proj_w
__device__ __align__(16) uint32_t g_wil[3 * 1024 * CW];
__device__ __align__(16) uint32_t g_woh[1024 * CW];        // out_w
__device__ __align__(16) uint32_t g_wol[1024 * CW];
__device__ __align__(16) uint32_t g_xh[M_ROWS * CW];       // attn out (N,B,C)
__device__ __align__(16) uint32_t g_xl[M_ROWS * CW];

// Attention operands
__device__ __align__(16) uint32_t g_qh[BH * N_SEQ * 32];   // [bh][n][dword]
__device__ __align__(16) uint32_t g_ql[BH * N_SEQ * 32];
__device__ __align__(16) uint32_t g_kh[BH * N_SEQ * 32];
__device__ __align__(16) uint32_t g_kl[BH * N_SEQ * 32];
__device__ __align__(16) __nv_bfloat16 g_vh16[BH * HD * N_SEQ];  // [bh][d][n]
__device__ __align__(16) __nv_bfloat16 g_vl16[BH * HD * N_SEQ];

// ---------------------------------------------------------------------------
// Helpers (plain-target PTX only)
// ---------------------------------------------------------------------------
__device__ __forceinline__ uint32_t smem_u32(const void* p) {
    uint32_t a;
    asm("{ .reg .u64 t; cvta.to.shared.u64 t, %1; cvt.u32.u64 %0, t; }"
        : "=r"(a) : "l"(p));
    return a;
}

#define CP_ASYNC16(dst, src) \
    asm volatile("cp.async.cg.shared.global [%0], [%1], 16;" \
                 :: "r"(dst), "l"(src))
#define CP_COMMIT()  asm volatile("cp.async.commit_group;" ::: "memory")
#define CP_WAIT0()   asm volatile("cp.async.wait_group 0;" ::: "memory")

__device__ __forceinline__ void ldsm_x4(uint32_t* r, uint32_t addr) {
    asm volatile("ldmatrix.sync.aligned.m8n8.x4.shared.b16 {%0,%1,%2,%3}, [%4];"
                 : "=r"(r[0]), "=r"(r[1]), "=r"(r[2]), "=r"(r[3]) : "r"(addr));
}

__device__ __forceinline__ void mma_bf16(float* d, const uint32_t* a,
                                         uint32_t b0, uint32_t b1) {
    asm volatile(
        "mma.sync.aligned.m16n8k16.row.col.f32.bf16.bf16.f32 "
        "{%0,%1,%2,%3}, {%4,%5,%6,%7}, {%8,%9}, {%0,%1,%2,%3};"
        : "+f"(d[0]), "+f"(d[1]), "+f"(d[2]), "+f"(d[3])
        : "r"(a[0]), "r"(a[1]), "r"(a[2]), "r"(a[3]), "r"(b0), "r"(b1));
}

__device__ __forceinline__ uint32_t pack_bf2(float x, float y) {
    uint16_t lx = __bfloat16_as_ushort(__float2bfloat16_rn(x));
    uint16_t ly = __bfloat16_as_ushort(__float2bfloat16_rn(y));
    return (uint32_t)lx | ((uint32_t)ly << 16);
}

__device__ __forceinline__ void split2(float x, float y, uint32_t& hw, uint32_t& lw) {
    float hx = __bfloat162float(__float2bfloat16_rn(x));
    float hy = __bfloat162float(__float2bfloat16_rn(y));
    hw = pack_bf2(hx, hy);
    lw = pack_bf2(x - hx, y - hy);
}

__device__ __forceinline__ float fast_exp2(float x) {
    float y;
    asm("ex2.approx.f32 %0, %1;" : "=f"(y) : "f"(x));
    return y;
}

// ---------------------------------------------------------------------------
// Kernel 0: merged split pre-pass. Flat index decodes region:
// [0,3*NI): q/k/v inputs -> g_inh/g_inl; [..+NWI): in_proj_w; [..+NWO): out_w.
// ---------------------------------------------------------------------------
#define NF4_IN (M_ROWS * C_DIM / 4)         // 1048576
#define NF4_WI (3 * 1024 * C_DIM / 4)       // 786432
#define NF4_WO (1024 * C_DIM / 4)           // 262144
#define NF4_TOTAL (3 * NF4_IN + NF4_WI + NF4_WO)   // 4194304

__global__ void __launch_bounds__(256) split_all(
    const float4* __restrict__ q, const float4* __restrict__ k,
    const float4* __restrict__ v, const float4* __restrict__ wi,
    const float4* __restrict__ wo)
{
    int i = blockIdx.x * blockDim.x + threadIdx.x;
    const float4* src;
    uint32_t *dh, *dl;
    int j;
    if (i < 3 * NF4_IN) {
        int which = i / NF4_IN;
        j = i - which * NF4_IN;
        src = (which == 0) ? q : (which == 1) ? k : v;
        dh = g_inh + (size_t)which * M_ROWS * CW;
        dl = g_inl + (size_t)which * M_ROWS * CW;
    } else if (i < 3 * NF4_IN + NF4_WI) {
        j = i - 3 * NF4_IN;
        src = wi;  dh = g_wih;  dl = g_wil;
    } else {
        j = i - 3 * NF4_IN - NF4_WI;
        src = wo;  dh = g_woh;  dl = g_wol;
    }
    float4 val = src[j];
    uint32_t h0, l0, h1, l1;
    split2(val.x, val.y, h0, l0);
    split2(val.z, val.w, h1, l1);
    size_t off = 2 * (size_t)j;
    dh[off] = h0; dh[off + 1] = h1;
    dl[off] = l0; dl[off + 1] = l1;
}

// ---------------------------------------------------------------------------
// Tensor-core GEMM, 3xBF16, pre-split operands (PROVEN R13, unchanged).
// ---------------------------------------------------------------------------
#define SW      20
#define PLANE_W (128 * SW)
#define STAGE_W (4 * PLANE_W)            // Ah, Al, Bh, Bl
#define GEMM_SMEM_BYTES (2 * STAGE_W * 4)   // 81920 bytes

__global__ void __launch_bounds__(256, 2) gemm_tc(
    const float* __restrict__ bias, float* __restrict__ dlin, int mode)
{
    extern __shared__ uint32_t sg[];
    const uint32_t sb = smem_u32(sg);

    const int z = blockIdx.z;
    const uint32_t* Agh = (mode == 1) ? g_xh : g_inh + (size_t)z * M_ROWS * CW;
    const uint32_t* Agl = (mode == 1) ? g_xl : g_inl + (size_t)z * M_ROWS * CW;
    const uint32_t* Bgh = (mode == 1) ? g_woh : g_wih + (size_t)z * 1024 * CW;
    const uint32_t* Bgl = (mode == 1) ? g_wol : g_wil + (size_t)z * 1024 * CW;
    const float* bp = bias + z * C_DIM;

    const int m0 = blockIdx.y * 128;
    const int n0 = blockIdx.x * 128;
    const int tid  = threadIdx.x;
    const int wid  = tid >> 5;
    const int lane = tid & 31;
    const int warp_m = wid >> 2;
    const int warp_n = wid & 3;

    float acc[4][4][4];
#pragma unroll
    for (int i = 0; i < 4; i++)
#pragma unroll
        for (int j = 0; j < 4; j++)
#pragma unroll
            for (int c = 0; c < 4; c++) acc[i][j][c] = 0.f;

    const int fr = tid >> 2;
    const int fc = (tid & 3) << 2;

#define ISSUE(kit) {                                                            \
        int _s = (kit) & 1;                                                     \
        int _kw = (kit) * 16;                                                   \
        _Pragma("unroll")                                                       \
        for (int u = 0; u < 2; u++) {                                           \
            int r = fr + 64 * u;                                                \
            uint32_t dst = sb + (uint32_t)(_s * STAGE_W + r * SW + fc) * 4;     \
            size_t ao = (size_t)(m0 + r) * CW + _kw + fc;                       \
            size_t bo = (size_t)(n0 + r) * CW + _kw + fc;                       \
            CP_ASYNC16(dst,                   Agh + ao);                        \
            CP_ASYNC16(dst + PLANE_W * 4,     Agl + ao);                        \
            CP_ASYNC16(dst + 2 * PLANE_W * 4, Bgh + bo);                        \
            CP_ASYNC16(dst + 3 * PLANE_W * 4, Bgl + bo);                        \
        }                                                                       \
        CP_COMMIT();                                                            \
    }

    const int arow_l = (lane & 7) + ((lane >> 3) & 1) * 8;
    const int awrd_l = (lane >> 4) * 4;
    uint32_t aoff[4];
#pragma unroll
    for (int mt = 0; mt < 4; mt++)
        aoff[mt] = (uint32_t)(((warp_m * 64 + mt * 16 + arow_l) * SW + awrd_l) * 4);
    const int brow_l = ((lane >> 4) * 8) + (lane & 7);
    const int bwrd_l = ((lane >> 3) & 1) * 4;
    uint32_t boff[2];
#pragma unroll
    for (int p = 0; p < 2; p++)
        boff[p] = (uint32_t)(((warp_n * 32 + p * 16 + brow_l) * SW + bwrd_l) * 4);

    const int NIT = C_DIM / 32;   // 32

    ISSUE(0);

    for (int it = 0; it < NIT; it++) {
        CP_WAIT0();
        __syncthreads();
        if (it + 1 < NIT) ISSUE(it + 1);

        const int s = it & 1;
        const uint32_t bAh = sb + (uint32_t)(s * STAGE_W) * 4;
        const uint32_t bAl = bAh + PLANE_W * 4;
        const uint32_t bBh = bAh + 2 * PLANE_W * 4;
        const uint32_t bBl = bAh + 3 * PLANE_W * 4;

#pragma unroll
        for (int ks = 0; ks < 2; ks++) {
            const uint32_t kb = (uint32_t)(ks * 32);

            uint32_t bh[2][4], bl[2][4];
            ldsm_x4(bh[0], bBh + boff[0] + kb);
            ldsm_x4(bh[1], bBh + boff[1] + kb);
            ldsm_x4(bl[0], bBl + boff[0] + kb);
            ldsm_x4(bl[1], bBl + boff[1] + kb);

            uint32_t ah[4][4], al[4][4];
#pragma unroll
            for (int mt = 0; mt < 4; mt++) {
                ldsm_x4(ah[mt], bAh + aoff[mt] + kb);
                ldsm_x4(al[mt], bAl + aoff[mt] + kb);
            }

#pragma unroll
            for (int mt = 0; mt < 4; mt++)
#pragma unroll
                for (int n8 = 0; n8 < 4; n8++) {
                    const int p = n8 >> 1, e = (n8 & 1) * 2;
                    mma_bf16(acc[mt][n8], ah[mt], bh[p][e], bh[p][e + 1]);
                }
#pragma unroll
            for (int mt = 0; mt < 4; mt++)
#pragma unroll
                for (int n8 = 0; n8 < 4; n8++) {
                    const int p = n8 >> 1, e = (n8 & 1) * 2;
                    mma_bf16(acc[mt][n8], ah[mt], bl[p][e], bl[p][e + 1]);
                }
#pragma unroll
            for (int mt = 0; mt < 4; mt++)
#pragma unroll
                for (int n8 = 0; n8 < 4; n8++) {
                    const int p = n8 >> 1, e = (n8 & 1) * 2;
                    mma_bf16(acc[mt][n8], al[mt], bh[p][e], bh[p][e + 1]);
                }
        }
    }
#undef ISSUE

    const int erow = lane >> 2;
    const int ecol = (lane & 3) * 2;
#pragma unroll
    for (int mt = 0; mt < 4; mt++) {
#pragma unroll
        for (int nt = 0; nt < 4; nt++) {
            int col = n0 + warp_n * 32 + nt * 8 + ecol;
            float bx = bp[col], by = bp[col + 1];
#pragma unroll
            for (int half = 0; half < 2; half++) {
                int m = m0 + warp_m * 64 + mt * 16 + erow + half * 8;
                float v0 = acc[mt][nt][half * 2 + 0] + bx;
                float v1 = acc[mt][nt][half * 2 + 1] + by;
                if (mode == 0) {
                    int n = m >> 2, bb = m & 3;
                    int h = col >> 6, d = col & 63;
                    if (z == 2) {
                        size_t base = ((size_t)(bb * H_NUM + h) * HD + d) * N_SEQ + n;
                        float h0 = __bfloat162float(__float2bfloat16_rn(v0));
                        float h1 = __bfloat162float(__float2bfloat16_rn(v1));
                        g_vh16[base]         = __float2bfloat16_rn(v0);
                        g_vl16[base]         = __float2bfloat16_rn(v0 - h0);
                        g_vh16[base + N_SEQ] = __float2bfloat16_rn(v1);
                        g_vl16[base + N_SEQ] = __float2bfloat16_rn(v1 - h1);
                    } else {
                        float* outp = (z == 0) ? g_qs : g_ks;
                        float2 vv = { v0, v1 };
                        *(float2*)(outp + (((size_t)(bb * H_NUM + h) * N_SEQ) + n) * HD + d) = vv;
                    }
                } else {
                    float2 vv = { v0, v1 };
                    *(float2*)(dlin + (size_t)m * C_DIM + col) = vv;
                }
            }
        }
    }
}

// ---------------------------------------------------------------------------
// Kernel 2: L2-normalize q/k rows (unchanged).
// ---------------------------------------------------------------------------
__global__ void __launch_bounds__(256) norm_kernel(const float* __restrict__ logit_scale)
{
    int wrow = (blockIdx.x * blockDim.x + threadIdx.x) >> 5;
    int lane = threadIdx.x & 31;
    const int rows_per_tensor = BH * N_SEQ;
    if (wrow >= 2 * rows_per_tensor) return;
    int which = wrow >= rows_per_tensor;
    int row = wrow - which * rows_per_tensor;
    const float* ptr = (which ? g_ks : g_qs) + (size_t)row * HD;

    float x0 = ptr[2 * lane];
    float x1 = ptr[2 * lane + 1];
    float ss = x0 * x0 + x1 * x1;
#pragma unroll
    for (int o = 16; o > 0; o >>= 1) ss += __shfl_xor_sync(0xffffffffu, ss, o);
    float scale = 1.0f / fmaxf(sqrtf(ss), 1e-12f);
    if (!which) {
        int h = (row >> 10) & 15;
        scale *= expf(fminf(logit_scale[h], LOGMAX)) * LOG2E;
    }
    uint32_t hw, lw;
    split2(x0 * scale, x1 * scale, hw, lw);
    uint32_t* dh = which ? g_kh : g_qh;
    uint32_t* dl = which ? g_kl : g_ql;
    dh[(size_t)row * 32 + lane] = hw;
    dl[(size_t)row * 32 + lane] = lw;
}

// ---------------------------------------------------------------------------
// Kernel 3: tensor-core flash attention with cp.async double-buffered K/V
// (R13 GEMM pipeline pattern applied verbatim). Block = 128 q x one head.
// ---------------------------------------------------------------------------
#define AW    36
#define Q_H   0
#define Q_L   (128 * AW)
#define KV_ST(s) (2 * 128 * AW + (s) * (4 * 64 * AW))
#define ATTN_SMEM_WORDS (2 * 128 * AW + 2 * 4 * 64 * AW)     // 27648 words
#define ATTN_SMEM_BYTES (ATTN_SMEM_WORDS * 4)                // 110592 bytes

__global__ void __launch_bounds__(256, 2) attn_kernel()
{
    extern __shared__ uint32_t sa[];
    const uint32_t sb = smem_u32(sa);

    const int bh = blockIdx.y;
    const int n0 = blockIdx.x * 128;
    const int tid  = threadIdx.x;
    const int warp = tid >> 5;
    const int lane = tid & 31;
    const int g    = lane >> 2;
    const int tig  = lane & 3;
    const int qr   = warp * 16;

    const size_t qrow0 = (size_t)bh * N_SEQ + n0;
    const size_t krow0 = (size_t)bh * N_SEQ;
    const size_t vrow0 = (size_t)bh * HD;
    const uint32_t* vwh = (const uint32_t*)g_vh16;
    const uint32_t* vwl = (const uint32_t*)g_vl16;

    // Stage Q (plain stores; first in-loop barrier publishes them)
#pragma unroll
    for (int u = 0; u < 4; u++) {
        int f = tid + 256 * u;
        int r = f >> 3, w4 = (f & 7) << 2;
        *(uint4*)&sa[Q_H + r * AW + w4] = *(const uint4*)&g_qh[(qrow0 + r) * 32 + w4];
        *(uint4*)&sa[Q_L + r * AW + w4] = *(const uint4*)&g_ql[(qrow0 + r) * 32 + w4];
    }

#define ISSUE_KV(kt) {                                                          \
        int _s = (kt) & 1;                                                      \
        uint32_t stb = sb + (uint32_t)KV_ST(_s) * 4;                            \
        _Pragma("unroll")                                                       \
        for (int u = 0; u < 2; u++) {                                           \
            int f = tid + 256 * u;                                              \
            int r = f >> 3, w4 = (f & 7) << 2;                                  \
            uint32_t dst = stb + (uint32_t)(r * AW + w4) * 4;                   \
            CP_ASYNC16(dst,                   &g_kh[(krow0 + (kt) * 64 + r) * 32 + w4]); \
            CP_ASYNC16(dst + 64 * AW * 4,     &g_kl[(krow0 + (kt) * 64 + r) * 32 + w4]); \
            CP_ASYNC16(dst + 2 * 64 * AW * 4, &vwh[(vrow0 + r) * 512 + (kt) * 32 + w4]); \
            CP_ASYNC16(dst + 3 * 64 * AW * 4, &vwl[(vrow0 + r) * 512 + (kt) * 32 + w4]); \
        }                                                                       \
        CP_COMMIT();                                                            \
    }

    float m0 = -1e30f, m1 = -1e30f, l0 = 0.f, l1 = 0.f;
    float o_acc[8][4];
#pragma unroll
    for (int i = 0; i < 8; i++)
#pragma unroll
        for (int c = 0; c < 4; c++) o_acc[i][c] = 0.f;

    ISSUE_KV(0);

    for (int kt = 0; kt < N_SEQ / 64; kt++) {
        CP_WAIT0();            // stage kt copy complete (this thread)
        __syncthreads();       // all visible; all warps done with prior stage
        if (kt + 1 < N_SEQ / 64) ISSUE_KV(kt + 1);   // overlaps compute below

        const int stW = KV_ST(kt & 1);
        const int sK_H = stW;
        const int sK_L = stW + 64 * AW;
        const int sV_H = stW + 2 * 64 * AW;
        const int sV_L = stW + 3 * 64 * AW;

        // ---- S = Q K^T, 3xbf16 ----
        float s_acc[8][4];
#pragma unroll
        for (int i = 0; i < 8; i++)
#pragma unroll
            for (int c = 0; c < 4; c++) s_acc[i][c] = 0.f;

#pragma unroll
        for (int s = 0; s < 4; s++) {
            const int kw = s * 8 + tig;
            const int rb = (qr + g) * AW;
            uint32_t qh[4], ql[4];
            qh[0] = sa[Q_H + rb + kw];          qh[1] = sa[Q_H + rb + 8 * AW + kw];
            qh[2] = sa[Q_H + rb + kw + 4];      qh[3] = sa[Q_H + rb + 8 * AW + kw + 4];
            ql[0] = sa[Q_L + rb + kw];          ql[1] = sa[Q_L + rb + 8 * AW + kw];
            ql[2] = sa[Q_L + rb + kw + 4];      ql[3] = sa[Q_L + rb + 8 * AW + kw + 4];
#pragma unroll
            for (int nt = 0; nt < 8; nt++) {
                int kb = (nt * 8 + g) * AW;
                uint32_t kh0 = sa[sK_H + kb + kw], kh1 = sa[sK_H + kb + kw + 4];
                uint32_t kl0 = sa[sK_L + kb + kw], kl1 = sa[sK_L + kb + kw + 4];
                mma_bf16(s_acc[nt], qh, kh0, kh1);
                mma_bf16(s_acc[nt], qh, kl0, kl1);
                mma_bf16(s_acc[nt], ql, kh0, kh1);
            }
        }

        // ---- online softmax (base-2) ----
        float rmax0 = -1e30f, rmax1 = -1e30f;
#pragma unroll
        for (int nt = 0; nt < 8; nt++) {
            rmax0 = fmaxf(rmax0, fmaxf(s_acc[nt][0], s_acc[nt][1]));
            rmax1 = fmaxf(rmax1, fmaxf(s_acc[nt][2], s_acc[nt][3]));
        }
        rmax0 = fmaxf(rmax0, __shfl_xor_sync(0xffffffffu, rmax0, 1));
        rmax0 = fmaxf(rmax0, __shfl_xor_sync(0xffffffffu, rmax0, 2));
        rmax1 = fmaxf(rmax1, __shfl_xor_sync(0xffffffffu, rmax1, 1));
        rmax1 = fmaxf(rmax1, __shfl_xor_sync(0xffffffffu, rmax1, 2));
        float mn0 = fmaxf(m0, rmax0), mn1 = fmaxf(m1, rmax1);
        float corr0 = fast_exp2(m0 - mn0), corr1 = fast_exp2(m1 - mn1);
        float rs0 = 0.f, rs1 = 0.f;
#pragma unroll
        for (int nt = 0; nt < 8; nt++) {
            s_acc[nt][0] = fast_exp2(s_acc[nt][0] - mn0);
            s_acc[nt][1] = fast_exp2(s_acc[nt][1] - mn0);
            s_acc[nt][2] = fast_exp2(s_acc[nt][2] - mn1);
            s_acc[nt][3] = fast_exp2(s_acc[nt][3] - mn1);
            rs0 += s_acc[nt][0] + s_acc[nt][1];
            rs1 += s_acc[nt][2] + s_acc[nt][3];
        }
        rs0 += __shfl_xor_sync(0xffffffffu, rs0, 1);
        rs0 += __shfl_xor_sync(0xffffffffu, rs0, 2);
        rs1 += __shfl_xor_sync(0xffffffffu, rs1, 1);
        rs1 += __shfl_xor_sync(0xffffffffu, rs1, 2);
        l0 = l0 * corr0 + rs0;  m0 = mn0;
        l1 = l1 * corr1 + rs1;  m1 = mn1;
#pragma unroll
        for (int nt = 0; nt < 8; nt++) {
            o_acc[nt][0] *= corr0;  o_acc[nt][1] *= corr0;
            o_acc[nt][2] *= corr1;  o_acc[nt][3] *= corr1;
        }

        // ---- O += P V ----
#pragma unroll
        for (int s = 0; s < 4; s++) {
            uint32_t pah[4], pal[4];
            split2(s_acc[2 * s][0],     s_acc[2 * s][1],     pah[0], pal[0]);
            split2(s_acc[2 * s][2],     s_acc[2 * s][3],     pah[1], pal[1]);
            split2(s_acc[2 * s + 1][0], s_acc[2 * s + 1][1], pah[2], pal[2]);
            split2(s_acc[2 * s + 1][2], s_acc[2 * s + 1][3], pah[3], pal[3]);
            const int kw = s * 8 + tig;
#pragma unroll
            for (int nt = 0; nt < 8; nt++) {
                int vb = (nt * 8 + g) * AW;
                uint32_t vh0 = sa[sV_H + vb + kw], vh1 = sa[sV_H + vb + kw + 4];
                uint32_t vl0 = sa[sV_L + vb + kw], vl1 = sa[sV_L + vb + kw + 4];
                mma_bf16(o_acc[nt], pah, vh0, vh1);
                mma_bf16(o_acc[nt], pah, vl0, vl1);
                mma_bf16(o_acc[nt], pal, vh0, vh1);
            }
        }
    }
#undef ISSUE_KV

    // Epilogue: out[q][d] = o/l, stored pre-split for the output projection
    const int bb = bh >> 4;
    const int h  = bh & 15;
    float inv0 = 1.0f / l0, inv1 = 1.0f / l1;
    int nq0 = n0 + qr + g;
    size_t row0 = ((size_t)nq0 * B_SZ + bb) * CW;
    size_t row1 = ((size_t)(nq0 + 8) * B_SZ + bb) * CW;
#pragma unroll
    for (int nt = 0; nt < 8; nt++) {
        int w = h * 32 + nt * 4 + tig;
        uint32_t hw, lw;
        split2(o_acc[nt][0] * inv0, o_acc[nt][1] * inv0, hw, lw);
        g_xh[row0 + w] = hw;  g_xl[row0 + w] = lw;
        split2(o_acc[nt][2] * inv1, o_acc[nt][3] * inv1, hw, lw);
        g_xh[row1 + w] = hw;  g_xl[row1 + w] = lw;
    }
}

// ---------------------------------------------------------------------------
extern "C" void kernel_launch(void* const* d_in, const int* in_sizes, int n_in,
                              void* d_out, int out_size)
{
    const float* q     = (const float*)d_in[0];
    const float* k     = (const float*)d_in[1];
    const float* v     = (const float*)d_in[2];
    const float* w_in  = (const float*)d_in[3];
    const float* b_in  = (const float*)d_in[4];
    const float* ls    = (const float*)d_in[5];
    const float* w_out = (const float*)d_in[6];
    const float* b_out = (const float*)d_in[7];
    float* out = (float*)d_out;

    cudaFuncSetAttribute(gemm_tc,
                         cudaFuncAttributeMaxDynamicSharedMemorySize,
                         GEMM_SMEM_BYTES);
    cudaFuncSetAttribute(attn_kernel,
                         cudaFuncAttributeMaxDynamicSharedMemorySize,
                         ATTN_SMEM_BYTES);

    split_all<<<NF4_TOTAL / 256, 256>>>(
        (const float4*)q, (const float4*)k, (const float4*)v,
        (const float4*)w_in, (const float4*)w_out);

    gemm_tc<<<dim3(C_DIM / 128, M_ROWS / 128, 3), 256, GEMM_SMEM_BYTES>>>(
        b_in, nullptr, 0);
    norm_kernel<<<(2 * BH * N_SEQ) / 8, 256>>>(ls);
    attn_kernel<<<dim3(N_SEQ / 128, BH), 256, ATTN_SMEM_BYTES>>>();
    gemm_tc<<<dim3(C_DIM / 128, M_ROWS / 128, 1), 256, GEMM_SMEM_BYTES>>>(
        b_out, out, 1);
}

// round 15
// speedup vs baseline: 1.7499x; 1.0203x over previous
#include <cuda_runtime.h>
#include <cuda_bf16.h>
#include <math.h>
#include <stdint.h>

// Problem constants
#define N_SEQ  1024
#define B_SZ   4
#define C_DIM  1024
#define H_NUM  16
#define HD     64
#define BH     64          // B*H
#define M_ROWS 4096        // N*B
#define CW     512         // 32-bit words per C_DIM row of packed bf16
#define LOGMAX 4.6051701859880913680f  // log(100)
#define LOG2E  1.4426950408889634f

// Scratch (static device arrays -- no allocations allowed)
__device__ float g_qs[BH * N_SEQ * HD];  // fp32 [bh][n][d] (pre-norm q)
__device__ float g_ks[BH * N_SEQ * HD];

// Pre-split bf16 hi/lo packed words (2 bf16 per uint32)
__device__ __align__(16) uint32_t g_inh[3 * M_ROWS * CW];  // q,k,v inputs
__device__ __align__(16) uint32_t g_inl[3 * M_ROWS * CW];
__device__ __align__(16) uint32_t g_wih[3 * 1024 * CW];    // in_proj_w
__device__ __align__(16) uint32_t g_wil[3 * 1024 * CW];
__device__ __align__(16) uint32_t g_woh[1024 * CW];        // out_w
__device__ __align__(16) uint32_t g_wol[1024 * CW];
__device__ __align__(16) uint32_t g_xh[M_ROWS * CW];       // attn out (N,B,C)
__device__ __align__(16) uint32_t g_xl[M_ROWS * CW];

// Attention operands
__device__ __align__(16) uint32_t g_qh[BH * N_SEQ * 32];   // [bh][n][dword]
__device__ __align__(16) uint32_t g_ql[BH * N_SEQ * 32];
__device__ __align__(16) uint32_t g_kh[BH * N_SEQ * 32];
__device__ __align__(16) uint32_t g_kl[BH * N_SEQ * 32];
__device__ __align__(16) __nv_bfloat16 g_vh16[BH * HD * N_SEQ];  // [bh][d][n]
__device__ __align__(16) __nv_bfloat16 g_vl16[BH * HD * N_SEQ];

// ---------------------------------------------------------------------------
// Helpers (plain-target PTX only)
// ---------------------------------------------------------------------------
__device__ __forceinline__ uint32_t smem_u32(const void* p) {
    uint32_t a;
    asm("{ .reg .u64 t; cvta.to.shared.u64 t, %1; cvt.u32.u64 %0, t; }"
        : "=r"(a) : "l"(p));
    return a;
}

#define CP_ASYNC16(dst, src) \
    asm volatile("cp.async.cg.shared.global [%0], [%1], 16;" \
                 :: "r"(dst), "l"(src))
#define CP_COMMIT()  asm volatile("cp.async.commit_group;" ::: "memory")
#define CP_WAIT0()   asm volatile("cp.async.wait_group 0;" ::: "memory")

__device__ __forceinline__ void ldsm_x4(uint32_t* r, uint32_t addr) {
    asm volatile("ldmatrix.sync.aligned.m8n8.x4.shared.b16 {%0,%1,%2,%3}, [%4];"
                 : "=r"(r[0]), "=r"(r[1]), "=r"(r[2]), "=r"(r[3]) : "r"(addr));
}

__device__ __forceinline__ void mma_bf16(float* d, const uint32_t* a,
                                         uint32_t b0, uint32_t b1) {
    asm volatile(
        "mma.sync.aligned.m16n8k16.row.col.f32.bf16.bf16.f32 "
        "{%0,%1,%2,%3}, {%4,%5,%6,%7}, {%8,%9}, {%0,%1,%2,%3};"
        : "+f"(d[0]), "+f"(d[1]), "+f"(d[2]), "+f"(d[3])
        : "r"(a[0]), "r"(a[1]), "r"(a[2]), "r"(a[3]), "r"(b0), "r"(b1));
}

__device__ __forceinline__ uint32_t pack_bf2(float x, float y) {
    uint16_t lx = __bfloat16_as_ushort(__float2bfloat16_rn(x));
    uint16_t ly = __bfloat16_as_ushort(__float2bfloat16_rn(y));
    return (uint32_t)lx | ((uint32_t)ly << 16);
}

__device__ __forceinline__ void split2(float x, float y, uint32_t& hw, uint32_t& lw) {
    float hx = __bfloat162float(__float2bfloat16_rn(x));
    float hy = __bfloat162float(__float2bfloat16_rn(y));
    hw = pack_bf2(hx, hy);
    lw = pack_bf2(x - hx, y - hy);
}

__device__ __forceinline__ float fast_exp2(float x) {
    float y;
    asm("ex2.approx.f32 %0, %1;" : "=f"(y) : "f"(x));
    return y;
}

// ---------------------------------------------------------------------------
// Kernel 0: merged split pre-pass (unchanged from R14).
// ---------------------------------------------------------------------------
#define NF4_IN (M_ROWS * C_DIM / 4)
#define NF4_WI (3 * 1024 * C_DIM / 4)
#define NF4_WO (1024 * C_DIM / 4)
#define NF4_TOTAL (3 * NF4_IN + NF4_WI + NF4_WO)

__global__ void __launch_bounds__(256) split_all(
    const float4* __restrict__ q, const float4* __restrict__ k,
    const float4* __restrict__ v, const float4* __restrict__ wi,
    const float4* __restrict__ wo)
{
    int i = blockIdx.x * blockDim.x + threadIdx.x;
    const float4* src;
    uint32_t *dh, *dl;
    int j;
    if (i < 3 * NF4_IN) {
        int which = i / NF4_IN;
        j = i - which * NF4_IN;
        src = (which == 0) ? q : (which == 1) ? k : v;
        dh = g_inh + (size_t)which * M_ROWS * CW;
        dl = g_inl + (size_t)which * M_ROWS * CW;
    } else if (i < 3 * NF4_IN + NF4_WI) {
        j = i - 3 * NF4_IN;
        src = wi;  dh = g_wih;  dl = g_wil;
    } else {
        j = i - 3 * NF4_IN - NF4_WI;
        src = wo;  dh = g_woh;  dl = g_wol;
    }
    float4 val = src[j];
    uint32_t h0, l0, h1, l1;
    split2(val.x, val.y, h0, l0);
    split2(val.z, val.w, h1, l1);
    size_t off = 2 * (size_t)j;
    dh[off] = h0; dh[off + 1] = h1;
    dl[off] = l0; dl[off + 1] = l1;
}

// ---------------------------------------------------------------------------
// Tensor-core GEMM, 3xBF16, pre-split operands (PROVEN R13, unchanged).
// ---------------------------------------------------------------------------
#define SW      20
#define PLANE_W (128 * SW)
#define STAGE_W (4 * PLANE_W)
#define GEMM_SMEM_BYTES (2 * STAGE_W * 4)   // 81920 bytes

__global__ void __launch_bounds__(256, 2) gemm_tc(
    const float* __restrict__ bias, float* __restrict__ dlin, int mode)
{
    extern __shared__ uint32_t sg[];
    const uint32_t sb = smem_u32(sg);

    const int z = blockIdx.z;
    const uint32_t* Agh = (mode == 1) ? g_xh : g_inh + (size_t)z * M_ROWS * CW;
    const uint32_t* Agl = (mode == 1) ? g_xl : g_inl + (size_t)z * M_ROWS * CW;
    const uint32_t* Bgh = (mode == 1) ? g_woh : g_wih + (size_t)z * 1024 * CW;
    const uint32_t* Bgl = (mode == 1) ? g_wol : g_wil + (size_t)z * 1024 * CW;
    const float* bp = bias + z * C_DIM;

    const int m0 = blockIdx.y * 128;
    const int n0 = blockIdx.x * 128;
    const int tid  = threadIdx.x;
    const int wid  = tid >> 5;
    const int lane = tid & 31;
    const int warp_m = wid >> 2;
    const int warp_n = wid & 3;

    float acc[4][4][4];
#pragma unroll
    for (int i = 0; i < 4; i++)
#pragma unroll
        for (int j = 0; j < 4; j++)
#pragma unroll
            for (int c = 0; c < 4; c++) acc[i][j][c] = 0.f;

    const int fr = tid >> 2;
    const int fc = (tid & 3) << 2;

#define ISSUE(kit) {                                                            \
        int _s = (kit) & 1;                                                     \
        int _kw = (kit) * 16;                                                   \
        _Pragma("unroll")                                                       \
        for (int u = 0; u < 2; u++) {                                           \
            int r = fr + 64 * u;                                                \
            uint32_t dst = sb + (uint32_t)(_s * STAGE_W + r * SW + fc) * 4;     \
            size_t ao = (size_t)(m0 + r) * CW + _kw + fc;                       \
            size_t bo = (size_t)(n0 + r) * CW + _kw + fc;                       \
            CP_ASYNC16(dst,                   Agh + ao);                        \
            CP_ASYNC16(dst + PLANE_W * 4,     Agl + ao);                        \
            CP_ASYNC16(dst + 2 * PLANE_W * 4, Bgh + bo);                        \
            CP_ASYNC16(dst + 3 * PLANE_W * 4, Bgl + bo);                        \
        }                                                                       \
        CP_COMMIT();                                                            \
    }

    const int arow_l = (lane & 7) + ((lane >> 3) & 1) * 8;
    const int awrd_l = (lane >> 4) * 4;
    uint32_t aoff[4];
#pragma unroll
    for (int mt = 0; mt < 4; mt++)
        aoff[mt] = (uint32_t)(((warp_m * 64 + mt * 16 + arow_l) * SW + awrd_l) * 4);
    const int brow_l = ((lane >> 4) * 8) + (lane & 7);
    const int bwrd_l = ((lane >> 3) & 1) * 4;
    uint32_t boff[2];
#pragma unroll
    for (int p = 0; p < 2; p++)
        boff[p] = (uint32_t)(((warp_n * 32 + p * 16 + brow_l) * SW + bwrd_l) * 4);

    const int NIT = C_DIM / 32;   // 32

    ISSUE(0);

    for (int it = 0; it < NIT; it++) {
        CP_WAIT0();
        __syncthreads();
        if (it + 1 < NIT) ISSUE(it + 1);

        const int s = it & 1;
        const uint32_t bAh = sb + (uint32_t)(s * STAGE_W) * 4;
        const uint32_t bAl = bAh + PLANE_W * 4;
        const uint32_t bBh = bAh + 2 * PLANE_W * 4;
        const uint32_t bBl = bAh + 3 * PLANE_W * 4;

#pragma unroll
        for (int ks = 0; ks < 2; ks++) {
            const uint32_t kb = (uint32_t)(ks * 32);

            uint32_t bh[2][4], bl[2][4];
            ldsm_x4(bh[0], bBh + boff[0] + kb);
            ldsm_x4(bh[1], bBh + boff[1] + kb);
            ldsm_x4(bl[0], bBl + boff[0] + kb);
            ldsm_x4(bl[1], bBl + boff[1] + kb);

            uint32_t ah[4][4], al[4][4];
#pragma unroll
            for (int mt = 0; mt < 4; mt++) {
                ldsm_x4(ah[mt], bAh + aoff[mt] + kb);
                ldsm_x4(al[mt], bAl + aoff[mt] + kb);
            }

#pragma unroll
            for (int mt = 0; mt < 4; mt++)
#pragma unroll
                for (int n8 = 0; n8 < 4; n8++) {
                    const int p = n8 >> 1, e = (n8 & 1) * 2;
                    mma_bf16(acc[mt][n8], ah[mt], bh[p][e], bh[p][e + 1]);
                }
#pragma unroll
            for (int mt = 0; mt < 4; mt++)
#pragma unroll
                for (int n8 = 0; n8 < 4; n8++) {
                    const int p = n8 >> 1, e = (n8 & 1) * 2;
                    mma_bf16(acc[mt][n8], ah[mt], bl[p][e], bl[p][e + 1]);
                }
#pragma unroll
            for (int mt = 0; mt < 4; mt++)
#pragma unroll
                for (int n8 = 0; n8 < 4; n8++) {
                    const int p = n8 >> 1, e = (n8 & 1) * 2;
                    mma_bf16(acc[mt][n8], al[mt], bh[p][e], bh[p][e + 1]);
                }
        }
    }
#undef ISSUE

    const int erow = lane >> 2;
    const int ecol = (lane & 3) * 2;
#pragma unroll
    for (int mt = 0; mt < 4; mt++) {
#pragma unroll
        for (int nt = 0; nt < 4; nt++) {
            int col = n0 + warp_n * 32 + nt * 8 + ecol;
            float bx = bp[col], by = bp[col + 1];
#pragma unroll
            for (int half = 0; half < 2; half++) {
                int m = m0 + warp_m * 64 + mt * 16 + erow + half * 8;
                float v0 = acc[mt][nt][half * 2 + 0] + bx;
                float v1 = acc[mt][nt][half * 2 + 1] + by;
                if (mode == 0) {
                    int n = m >> 2, bb = m & 3;
                    int h = col >> 6, d = col & 63;
                    if (z == 2) {
                        size_t base = ((size_t)(bb * H_NUM + h) * HD + d) * N_SEQ + n;
                        float h0 = __bfloat162float(__float2bfloat16_rn(v0));
                        float h1 = __bfloat162float(__float2bfloat16_rn(v1));
                        g_vh16[base]         = __float2bfloat16_rn(v0);
                        g_vl16[base]         = __float2bfloat16_rn(v0 - h0);
                        g_vh16[base + N_SEQ] = __float2bfloat16_rn(v1);
                        g_vl16[base + N_SEQ] = __float2bfloat16_rn(v1 - h1);
                    } else {
                        float* outp = (z == 0) ? g_qs : g_ks;
                        float2 vv = { v0, v1 };
                        *(float2*)(outp + (((size_t)(bb * H_NUM + h) * N_SEQ) + n) * HD + d) = vv;
                    }
                } else {
                    float2 vv = { v0, v1 };
                    *(float2*)(dlin + (size_t)m * C_DIM + col) = vv;
                }
            }
        }
    }
}

// ---------------------------------------------------------------------------
// Kernel 2: L2-normalize q/k rows (unchanged).
// ---------------------------------------------------------------------------
__global__ void __launch_bounds__(256) norm_kernel(const float* __restrict__ logit_scale)
{
    int wrow = (blockIdx.x * blockDim.x + threadIdx.x) >> 5;
    int lane = threadIdx.x & 31;
    const int rows_per_tensor = BH * N_SEQ;
    if (wrow >= 2 * rows_per_tensor) return;
    int which = wrow >= rows_per_tensor;
    int row = wrow - which * rows_per_tensor;
    const float* ptr = (which ? g_ks : g_qs) + (size_t)row * HD;

    float x0 = ptr[2 * lane];
    float x1 = ptr[2 * lane + 1];
    float ss = x0 * x0 + x1 * x1;
#pragma unroll
    for (int o = 16; o > 0; o >>= 1) ss += __shfl_xor_sync(0xffffffffu, ss, o);
    float scale = 1.0f / fmaxf(sqrtf(ss), 1e-12f);
    if (!which) {
        int h = (row >> 10) & 15;
        scale *= expf(fminf(logit_scale[h], LOGMAX)) * LOG2E;
    }
    uint32_t hw, lw;
    split2(x0 * scale, x1 * scale, hw, lw);
    uint32_t* dh = which ? g_kh : g_qh;
    uint32_t* dl = which ? g_kl : g_ql;
    dh[(size_t)row * 32 + lane] = hw;
    dl[(size_t)row * 32 + lane] = lw;
}

// ---------------------------------------------------------------------------
// Kernel 3: tensor-core flash attention, cp.async K/V double buffer (R14)
// + ldmatrix fragment loads + term-major MMA ordering (proven R12/R13 recipe).
// Block = 128 q x one head; 8 warps, 16 query rows each.
// AW=36 rows: 144B (16B-aligned); 8-row ldsm fetch -> banks {4r mod 32},
// all-disjoint => conflict-free.
// ---------------------------------------------------------------------------
#define AW    36
#define Q_H   0
#define Q_L   (128 * AW)
#define KV_ST(s) (2 * 128 * AW + (s) * (4 * 64 * AW))
#define ATTN_SMEM_WORDS (2 * 128 * AW + 2 * 4 * 64 * AW)     // 27648 words
#define ATTN_SMEM_BYTES (ATTN_SMEM_WORDS * 4)                // 110592 bytes

__global__ void __launch_bounds__(256, 2) attn_kernel()
{
    extern __shared__ uint32_t sa[];
    const uint32_t sb = smem_u32(sa);

    const int bh = blockIdx.y;
    const int n0 = blockIdx.x * 128;
    const int tid  = threadIdx.x;
    const int warp = tid >> 5;
    const int lane = tid & 31;
    const int g    = lane >> 2;
    const int tig  = lane & 3;
    const int qr   = warp * 16;

    const size_t qrow0 = (size_t)bh * N_SEQ + n0;
    const size_t krow0 = (size_t)bh * N_SEQ;
    const size_t vrow0 = (size_t)bh * HD;
    const uint32_t* vwh = (const uint32_t*)g_vh16;
    const uint32_t* vwl = (const uint32_t*)g_vl16;

    // Stage Q (plain stores; first in-loop barrier publishes them)
#pragma unroll
    for (int u = 0; u < 4; u++) {
        int f = tid + 256 * u;
        int r = f >> 3, w4 = (f & 7) << 2;
        *(uint4*)&sa[Q_H + r * AW + w4] = *(const uint4*)&g_qh[(qrow0 + r) * 32 + w4];
        *(uint4*)&sa[Q_L + r * AW + w4] = *(const uint4*)&g_ql[(qrow0 + r) * 32 + w4];
    }

#define ISSUE_KV(kt) {                                                          \
        int _s = (kt) & 1;                                                      \
        uint32_t stb = sb + (uint32_t)KV_ST(_s) * 4;                            \
        _Pragma("unroll")                                                       \
        for (int u = 0; u < 2; u++) {                                           \
            int f = tid + 256 * u;                                              \
            int r = f >> 3, w4 = (f & 7) << 2;                                  \
            uint32_t dst = stb + (uint32_t)(r * AW + w4) * 4;                   \
            CP_ASYNC16(dst,                   &g_kh[(krow0 + (kt) * 64 + r) * 32 + w4]); \
            CP_ASYNC16(dst + 64 * AW * 4,     &g_kl[(krow0 + (kt) * 64 + r) * 32 + w4]); \
            CP_ASYNC16(dst + 2 * 64 * AW * 4, &vwh[(vrow0 + r) * 512 + (kt) * 32 + w4]); \
            CP_ASYNC16(dst + 3 * 64 * AW * 4, &vwl[(vrow0 + r) * 512 + (kt) * 32 + w4]); \
        }                                                                       \
        CP_COMMIT();                                                            \
    }

    // ldmatrix lane-address components (proven GEMM maps)
    const int arow_l = (lane & 7) + ((lane >> 3) & 1) * 8;
    const int awrd_l = (lane >> 4) * 4;
    const uint32_t qoff = (uint32_t)(((qr + arow_l) * AW + awrd_l) * 4);
    const int brow_l = ((lane >> 4) * 8) + (lane & 7);
    const int bwrd_l = ((lane >> 3) & 1) * 4;
    uint32_t kvoff[4];
#pragma unroll
    for (int p = 0; p < 4; p++)
        kvoff[p] = (uint32_t)(((p * 16 + brow_l) * AW + bwrd_l) * 4);

    const uint32_t sbQ_H = sb + (uint32_t)Q_H * 4;
    const uint32_t sbQ_L = sb + (uint32_t)Q_L * 4;

    float m0 = -1e30f, m1 = -1e30f, l0 = 0.f, l1 = 0.f;
    float o_acc[8][4];
#pragma unroll
    for (int i = 0; i < 8; i++)
#pragma unroll
        for (int c = 0; c < 4; c++) o_acc[i][c] = 0.f;

    ISSUE_KV(0);

    for (int kt = 0; kt < N_SEQ / 64; kt++) {
        CP_WAIT0();
        __syncthreads();
        if (kt + 1 < N_SEQ / 64) ISSUE_KV(kt + 1);

        const uint32_t stB  = sb + (uint32_t)KV_ST(kt & 1) * 4;
        const uint32_t bK_H = stB;
        const uint32_t bK_L = stB + 64 * AW * 4;
        const uint32_t bV_H = stB + 2 * 64 * AW * 4;
        const uint32_t bV_L = stB + 3 * 64 * AW * 4;

        // ---- S = Q K^T, 3xbf16, ldmatrix + term-major ----
        float s_acc[8][4];
#pragma unroll
        for (int i = 0; i < 8; i++)
#pragma unroll
            for (int c = 0; c < 4; c++) s_acc[i][c] = 0.f;

#pragma unroll
        for (int s = 0; s < 4; s++) {
            const uint32_t kb = (uint32_t)(s * 32);   // k16 step = 8 words

            uint32_t qh[4], ql[4];
            ldsm_x4(qh, sbQ_H + qoff + kb);
            ldsm_x4(ql, sbQ_L + qoff + kb);

            uint32_t kh[4][4], kl[4][4];
#pragma unroll
            for (int p = 0; p < 4; p++) {
                ldsm_x4(kh[p], bK_H + kvoff[p] + kb);
                ldsm_x4(kl[p], bK_L + kvoff[p] + kb);
            }

#pragma unroll
            for (int nt = 0; nt < 8; nt++) {
                const int p = nt >> 1, e = (nt & 1) * 2;
                mma_bf16(s_acc[nt], qh, kh[p][e], kh[p][e + 1]);
            }
#pragma unroll
            for (int nt = 0; nt < 8; nt++) {
                const int p = nt >> 1, e = (nt & 1) * 2;
                mma_bf16(s_acc[nt], qh, kl[p][e], kl[p][e + 1]);
            }
#pragma unroll
            for (int nt = 0; nt < 8; nt++) {
                const int p = nt >> 1, e = (nt & 1) * 2;
                mma_bf16(s_acc[nt], ql, kh[p][e], kh[p][e + 1]);
            }
        }

        // ---- online softmax (base-2) ----
        float rmax0 = -1e30f, rmax1 = -1e30f;
#pragma unroll
        for (int nt = 0; nt < 8; nt++) {
            rmax0 = fmaxf(rmax0, fmaxf(s_acc[nt][0], s_acc[nt][1]));
            rmax1 = fmaxf(rmax1, fmaxf(s_acc[nt][2], s_acc[nt][3]));
        }
        rmax0 = fmaxf(rmax0, __shfl_xor_sync(0xffffffffu, rmax0, 1));
        rmax0 = fmaxf(rmax0, __shfl_xor_sync(0xffffffffu, rmax0, 2));
        rmax1 = fmaxf(rmax1, __shfl_xor_sync(0xffffffffu, rmax1, 1));
        rmax1 = fmaxf(rmax1, __shfl_xor_sync(0xffffffffu, rmax1, 2));
        float mn0 = fmaxf(m0, rmax0), mn1 = fmaxf(m1, rmax1);
        float corr0 = fast_exp2(m0 - mn0), corr1 = fast_exp2(m1 - mn1);
        float rs0 = 0.f, rs1 = 0.f;
#pragma unroll
        for (int nt = 0; nt < 8; nt++) {
            s_acc[nt][0] = fast_exp2(s_acc[nt][0] - mn0);
            s_acc[nt][1] = fast_exp2(s_acc[nt][1] - mn0);
            s_acc[nt][2] = fast_exp2(s_acc[nt][2] - mn1);
            s_acc[nt][3] = fast_exp2(s_acc[nt][3] - mn1);
            rs0 += s_acc[nt][0] + s_acc[nt][1];
            rs1 += s_acc[nt][2] + s_acc[nt][3];
        }
        rs0 += __shfl_xor_sync(0xffffffffu, rs0, 1);
        rs0 += __shfl_xor_sync(0xffffffffu, rs0, 2);
        rs1 += __shfl_xor_sync(0xffffffffu, rs1, 1);
        rs1 += __shfl_xor_sync(0xffffffffu, rs1, 2);
        l0 = l0 * corr0 + rs0;  m0 = mn0;
        l1 = l1 * corr1 + rs1;  m1 = mn1;
#pragma unroll
        for (int nt = 0; nt < 8; nt++) {
            o_acc[nt][0] *= corr0;  o_acc[nt][1] *= corr0;
            o_acc[nt][2] *= corr1;  o_acc[nt][3] *= corr1;
        }

        // ---- O += P V, ldmatrix V + term-major ----
#pragma unroll
        for (int s = 0; s < 4; s++) {
            uint32_t pah[4], pal[4];
            split2(s_acc[2 * s][0],     s_acc[2 * s][1],     pah[0], pal[0]);
            split2(s_acc[2 * s][2],     s_acc[2 * s][3],     pah[1], pal[1]);
            split2(s_acc[2 * s + 1][0], s_acc[2 * s + 1][1], pah[2], pal[2]);
            split2(s_acc[2 * s + 1][2], s_acc[2 * s + 1][3], pah[3], pal[3]);
            const uint32_t kb = (uint32_t)(s * 32);

            uint32_t vh[4][4], vl[4][4];
#pragma unroll
            for (int p = 0; p < 4; p++) {
                ldsm_x4(vh[p], bV_H + kvoff[p] + kb);
                ldsm_x4(vl[p], bV_L + kvoff[p] + kb);
            }

#pragma unroll
            for (int nt = 0; nt < 8; nt++) {
                const int p = nt >> 1, e = (nt & 1) * 2;
                mma_bf16(o_acc[nt], pah, vh[p][e], vh[p][e + 1]);
            }
#pragma unroll
            for (int nt = 0; nt < 8; nt++) {
                const int p = nt >> 1, e = (nt & 1) * 2;
                mma_bf16(o_acc[nt], pah, vl[p][e], vl[p][e + 1]);
            }
#pragma unroll
            for (int nt = 0; nt < 8; nt++) {
                const int p = nt >> 1, e = (nt & 1) * 2;
                mma_bf16(o_acc[nt], pal, vh[p][e], vh[p][e + 1]);
            }
        }
    }
#undef ISSUE_KV

    // Epilogue: out[q][d] = o/l, stored pre-split for the output projection
    const int bb = bh >> 4;
    const int h  = bh & 15;
    float inv0 = 1.0f / l0, inv1 = 1.0f / l1;
    int nq0 = n0 + qr + g;
    size_t row0 = ((size_t)nq0 * B_SZ + bb) * CW;
    size_t row1 = ((size_t)(nq0 + 8) * B_SZ + bb) * CW;
#pragma unroll
    for (int nt = 0; nt < 8; nt++) {
        int w = h * 32 + nt * 4 + tig;
        uint32_t hw, lw;
        split2(o_acc[nt][0] * inv0, o_acc[nt][1] * inv0, hw, lw);
        g_xh[row0 + w] = hw;  g_xl[row0 + w] = lw;
        split2(o_acc[nt][2] * inv1, o_acc[nt][3] * inv1, hw, lw);
        g_xh[row1 + w] = hw;  g_xl[row1 + w] = lw;
    }
}

// ---------------------------------------------------------------------------
extern "C" void kernel_launch(void* const* d_in, const int* in_sizes, int n_in,
                              void* d_out, int out_size)
{
    const float* q     = (const float*)d_in[0];
    const float* k     = (const float*)d_in[1];
    const float* v     = (const float*)d_in[2];
    const float* w_in  = (const float*)d_in[3];
    const float* b_in  = (const float*)d_in[4];
    const float* ls    = (const float*)d_in[5];
    const float* w_out = (const float*)d_in[6];
    const float* b_out = (const float*)d_in[7];
    float* out = (float*)d_out;

    cudaFuncSetAttribute(gemm_tc,
                         cudaFuncAttributeMaxDynamicSharedMemorySize,
                         GEMM_SMEM_BYTES);
    cudaFuncSetAttribute(attn_kernel,
                         cudaFuncAttributeMaxDynamicSharedMemorySize,
                         ATTN_SMEM_BYTES);

    split_all<<<NF4_TOTAL / 256, 256>>>(
        (const float4*)q, (const float4*)k, (const float4*)v,
        (const float4*)w_in, (const float4*)w_out);

    gemm_tc<<<dim3(C_DIM / 128, M_ROWS / 128, 3), 256, GEMM_SMEM_BYTES>>>(
        b_in, nullptr, 0);
    norm_kernel<<<(2 * BH * N_SEQ) / 8, 256>>>(ls);
    attn_kernel<<<dim3(N_SEQ / 128, BH), 256, ATTN_SMEM_BYTES>>>();
    gemm_tc<<<dim3(C_DIM / 128, M_ROWS / 128, 1), 256, GEMM_SMEM_BYTES>>>(
        b_out, out, 1);
}

// round 16
// speedup vs baseline: 1.8557x; 1.0605x over previous
#include <cuda_runtime.h>
#include <cuda_bf16.h>
#include <cuda_fp16.h>
#include <math.h>
#include <stdint.h>

// Problem constants
#define N_SEQ  1024
#define B_SZ   4
#define C_DIM  1024
#define H_NUM  16
#define HD     64
#define BH     64          // B*H
#define M_ROWS 4096        // N*B
#define CW     512         // 32-bit words per C_DIM row of packed bf16
#define LOGMAX 4.6051701859880913680f  // log(100)
#define LOG2E  1.4426950408889634f

// Scratch (static device arrays -- no allocations allowed)
__device__ float g_qs[BH * N_SEQ * HD];  // fp32 [bh][n][d] (pre-norm q)
__device__ float g_ks[BH * N_SEQ * HD];

// Pre-split bf16 hi/lo packed words (2 bf16 per uint32)
__device__ __align__(16) uint32_t g_inh[3 * M_ROWS * CW];  // q,k,v inputs
__device__ __align__(16) uint32_t g_inl[3 * M_ROWS * CW];
__device__ __align__(16) uint32_t g_wih[3 * 1024 * CW];    // in_proj_w
__device__ __align__(16) uint32_t g_wil[3 * 1024 * CW];
__device__ __align__(16) uint32_t g_woh[1024 * CW];        // out_w
__device__ __align__(16) uint32_t g_wol[1024 * CW];
__device__ __align__(16) uint32_t g_xh[M_ROWS * CW];       // attn out (N,B,C)
__device__ __align__(16) uint32_t g_xl[M_ROWS * CW];

// Attention operands (q/k packed bf16 hi/lo; V transposed fp16 hi/lo)
__device__ __align__(16) uint32_t g_qh[BH * N_SEQ * 32];   // [bh][n][dword]
__device__ __align__(16) uint32_t g_ql[BH * N_SEQ * 32];
__device__ __align__(16) uint32_t g_kh[BH * N_SEQ * 32];
__device__ __align__(16) uint32_t g_kl[BH * N_SEQ * 32];
__device__ __align__(16) __half g_vh16[BH * HD * N_SEQ];   // [bh][d][n] V^T hi
__device__ __align__(16) __half g_vl16[BH * HD * N_SEQ];   // lo

// ---------------------------------------------------------------------------
// Helpers (plain-target PTX only)
// ---------------------------------------------------------------------------
__device__ __forceinline__ uint32_t smem_u32(const void* p) {
    uint32_t a;
    asm("{ .reg .u64 t; cvta.to.shared.u64 t, %1; cvt.u32.u64 %0, t; }"
        : "=r"(a) : "l"(p));
    return a;
}

#define CP_ASYNC16(dst, src) \
    asm volatile("cp.async.cg.shared.global [%0], [%1], 16;" \
                 :: "r"(dst), "l"(src))
#define CP_COMMIT()  asm volatile("cp.async.commit_group;" ::: "memory")
#define CP_WAIT0()   asm volatile("cp.async.wait_group 0;" ::: "memory")

__device__ __forceinline__ void ldsm_x4(uint32_t* r, uint32_t addr) {
    asm volatile("ldmatrix.sync.aligned.m8n8.x4.shared.b16 {%0,%1,%2,%3}, [%4];"
                 : "=r"(r[0]), "=r"(r[1]), "=r"(r[2]), "=r"(r[3]) : "r"(addr));
}

__device__ __forceinline__ void mma_bf16(float* d, const uint32_t* a,
                                         uint32_t b0, uint32_t b1) {
    asm volatile(
        "mma.sync.aligned.m16n8k16.row.col.f32.bf16.bf16.f32 "
        "{%0,%1,%2,%3}, {%4,%5,%6,%7}, {%8,%9}, {%0,%1,%2,%3};"
        : "+f"(d[0]), "+f"(d[1]), "+f"(d[2]), "+f"(d[3])
        : "r"(a[0]), "r"(a[1]), "r"(a[2]), "r"(a[3]), "r"(b0), "r"(b1));
}

__device__ __forceinline__ void mma_f16(float* d, const uint32_t* a,
                                        uint32_t b0, uint32_t b1) {
    asm volatile(
        "mma.sync.aligned.m16n8k16.row.col.f32.f16.f16.f32 "
        "{%0,%1,%2,%3}, {%4,%5,%6,%7}, {%8,%9}, {%0,%1,%2,%3};"
        : "+f"(d[0]), "+f"(d[1]), "+f"(d[2]), "+f"(d[3])
        : "r"(a[0]), "r"(a[1]), "r"(a[2]), "r"(a[3]), "r"(b0), "r"(b1));
}

__device__ __forceinline__ uint32_t pack_bf2(float x, float y) {
    uint16_t lx = __bfloat16_as_ushort(__float2bfloat16_rn(x));
    uint16_t ly = __bfloat16_as_ushort(__float2bfloat16_rn(y));
    return (uint32_t)lx | ((uint32_t)ly << 16);
}

__device__ __forceinline__ void split2(float x, float y, uint32_t& hw, uint32_t& lw) {
    float hx = __bfloat162float(__float2bfloat16_rn(x));
    float hy = __bfloat162float(__float2bfloat16_rn(y));
    hw = pack_bf2(hx, hy);
    lw = pack_bf2(x - hx, y - hy);
}

// pack two fp32 -> f16x2 word: first operand -> HIGH half, second -> LOW half
__device__ __forceinline__ uint32_t pack_f16x2(float hi, float lo) {
    uint32_t r;
    asm("cvt.rn.f16x2.f32 %0, %1, %2;" : "=r"(r) : "f"(hi), "f"(lo));
    return r;
}

__device__ __forceinline__ float fast_exp2(float x) {
    float y;
    asm("ex2.approx.f32 %0, %1;" : "=f"(y) : "f"(x));
    return y;
}

// ---------------------------------------------------------------------------
// Kernel 0: merged split pre-pass (unchanged).
// ---------------------------------------------------------------------------
#define NF4_IN (M_ROWS * C_DIM / 4)
#define NF4_WI (3 * 1024 * C_DIM / 4)
#define NF4_WO (1024 * C_DIM / 4)
#define NF4_TOTAL (3 * NF4_IN + NF4_WI + NF4_WO)

__global__ void __launch_bounds__(256) split_all(
    const float4* __restrict__ q, const float4* __restrict__ k,
    const float4* __restrict__ v, const float4* __restrict__ wi,
    const float4* __restrict__ wo)
{
    int i = blockIdx.x * blockDim.x + threadIdx.x;
    const float4* src;
    uint32_t *dh, *dl;
    int j;
    if (i < 3 * NF4_IN) {
        int which = i / NF4_IN;
        j = i - which * NF4_IN;
        src = (which == 0) ? q : (which == 1) ? k : v;
        dh = g_inh + (size_t)which * M_ROWS * CW;
        dl = g_inl + (size_t)which * M_ROWS * CW;
    } else if (i < 3 * NF4_IN + NF4_WI) {
        j = i - 3 * NF4_IN;
        src = wi;  dh = g_wih;  dl = g_wil;
    } else {
        j = i - 3 * NF4_IN - NF4_WI;
        src = wo;  dh = g_woh;  dl = g_wol;
    }
    float4 val = src[j];
    uint32_t h0, l0, h1, l1;
    split2(val.x, val.y, h0, l0);
    split2(val.z, val.w, h1, l1);
    size_t off = 2 * (size_t)j;
    dh[off] = h0; dh[off + 1] = h1;
    dl[off] = l0; dl[off + 1] = l1;
}

// ---------------------------------------------------------------------------
// Tensor-core GEMM, 3xBF16 (PROVEN R13; only z==2 epilogue now emits fp16 V).
// ---------------------------------------------------------------------------
#define SW      20
#define PLANE_W (128 * SW)
#define STAGE_W (4 * PLANE_W)
#define GEMM_SMEM_BYTES (2 * STAGE_W * 4)   // 81920 bytes

__global__ void __launch_bounds__(256, 2) gemm_tc(
    const float* __restrict__ bias, float* __restrict__ dlin, int mode)
{
    extern __shared__ uint32_t sg[];
    const uint32_t sb = smem_u32(sg);

    const int z = blockIdx.z;
    const uint32_t* Agh = (mode == 1) ? g_xh : g_inh + (size_t)z * M_ROWS * CW;
    const uint32_t* Agl = (mode == 1) ? g_xl : g_inl + (size_t)z * M_ROWS * CW;
    const uint32_t* Bgh = (mode == 1) ? g_woh : g_wih + (size_t)z * 1024 * CW;
    const uint32_t* Bgl = (mode == 1) ? g_wol : g_wil + (size_t)z * 1024 * CW;
    const float* bp = bias + z * C_DIM;

    const int m0 = blockIdx.y * 128;
    const int n0 = blockIdx.x * 128;
    const int tid  = threadIdx.x;
    const int wid  = tid >> 5;
    const int lane = tid & 31;
    const int warp_m = wid >> 2;
    const int warp_n = wid & 3;

    float acc[4][4][4];
#pragma unroll
    for (int i = 0; i < 4; i++)
#pragma unroll
        for (int j = 0; j < 4; j++)
#pragma unroll
            for (int c = 0; c < 4; c++) acc[i][j][c] = 0.f;

    const int fr = tid >> 2;
    const int fc = (tid & 3) << 2;

#define ISSUE(kit) {                                                            \
        int _s = (kit) & 1;                                                     \
        int _kw = (kit) * 16;                                                   \
        _Pragma("unroll")                                                       \
        for (int u = 0; u < 2; u++) {                                           \
            int r = fr + 64 * u;                                                \
            uint32_t dst = sb + (uint32_t)(_s * STAGE_W + r * SW + fc) * 4;     \
            size_t ao = (size_t)(m0 + r) * CW + _kw + fc;                       \
            size_t bo = (size_t)(n0 + r) * CW + _kw + fc;                       \
            CP_ASYNC16(dst,                   Agh + ao);                        \
            CP_ASYNC16(dst + PLANE_W * 4,     Agl + ao);                        \
            CP_ASYNC16(dst + 2 * PLANE_W * 4, Bgh + bo);                        \
            CP_ASYNC16(dst + 3 * PLANE_W * 4, Bgl + bo);                        \
        }                                                                       \
        CP_COMMIT();                                                            \
    }

    const int arow_l = (lane & 7) + ((lane >> 3) & 1) * 8;
    const int awrd_l = (lane >> 4) * 4;
    uint32_t aoff[4];
#pragma unroll
    for (int mt = 0; mt < 4; mt++)
        aoff[mt] = (uint32_t)(((warp_m * 64 + mt * 16 + arow_l) * SW + awrd_l) * 4);
    const int brow_l = ((lane >> 4) * 8) + (lane & 7);
    const int bwrd_l = ((lane >> 3) & 1) * 4;
    uint32_t boff[2];
#pragma unroll
    for (int p = 0; p < 2; p++)
        boff[p] = (uint32_t)(((warp_n * 32 + p * 16 + brow_l) * SW + bwrd_l) * 4);

    const int NIT = C_DIM / 32;   // 32

    ISSUE(0);

    for (int it = 0; it < NIT; it++) {
        CP_WAIT0();
        __syncthreads();
        if (it + 1 < NIT) ISSUE(it + 1);

        const int s = it & 1;
        const uint32_t bAh = sb + (uint32_t)(s * STAGE_W) * 4;
        const uint32_t bAl = bAh + PLANE_W * 4;
        const uint32_t bBh = bAh + 2 * PLANE_W * 4;
        const uint32_t bBl = bAh + 3 * PLANE_W * 4;

#pragma unroll
        for (int ks = 0; ks < 2; ks++) {
            const uint32_t kb = (uint32_t)(ks * 32);

            uint32_t bh[2][4], bl[2][4];
            ldsm_x4(bh[0], bBh + boff[0] + kb);
            ldsm_x4(bh[1], bBh + boff[1] + kb);
            ldsm_x4(bl[0], bBl + boff[0] + kb);
            ldsm_x4(bl[1], bBl + boff[1] + kb);

            uint32_t ah[4][4], al[4][4];
#pragma unroll
            for (int mt = 0; mt < 4; mt++) {
                ldsm_x4(ah[mt], bAh + aoff[mt] + kb);
                ldsm_x4(al[mt], bAl + aoff[mt] + kb);
            }

#pragma unroll
            for (int mt = 0; mt < 4; mt++)
#pragma unroll
                for (int n8 = 0; n8 < 4; n8++) {
                    const int p = n8 >> 1, e = (n8 & 1) * 2;
                    mma_bf16(acc[mt][n8], ah[mt], bh[p][e], bh[p][e + 1]);
                }
#pragma unroll
            for (int mt = 0; mt < 4; mt++)
#pragma unroll
                for (int n8 = 0; n8 < 4; n8++) {
                    const int p = n8 >> 1, e = (n8 & 1) * 2;
                    mma_bf16(acc[mt][n8], ah[mt], bl[p][e], bl[p][e + 1]);
                }
#pragma unroll
            for (int mt = 0; mt < 4; mt++)
#pragma unroll
                for (int n8 = 0; n8 < 4; n8++) {
                    const int p = n8 >> 1, e = (n8 & 1) * 2;
                    mma_bf16(acc[mt][n8], al[mt], bh[p][e], bh[p][e + 1]);
                }
        }
    }
#undef ISSUE

    const int erow = lane >> 2;
    const int ecol = (lane & 3) * 2;
#pragma unroll
    for (int mt = 0; mt < 4; mt++) {
#pragma unroll
        for (int nt = 0; nt < 4; nt++) {
            int col = n0 + warp_n * 32 + nt * 8 + ecol;
            float bx = bp[col], by = bp[col + 1];
#pragma unroll
            for (int half = 0; half < 2; half++) {
                int m = m0 + warp_m * 64 + mt * 16 + erow + half * 8;
                float v0 = acc[mt][nt][half * 2 + 0] + bx;
                float v1 = acc[mt][nt][half * 2 + 1] + by;
                if (mode == 0) {
                    int n = m >> 2, bb = m & 3;
                    int h = col >> 6, d = col & 63;
                    if (z == 2) {
                        // V: transposed fp16 hi/lo  [bh][d][n]
                        size_t base = ((size_t)(bb * H_NUM + h) * HD + d) * N_SEQ + n;
                        __half h0 = __float2half_rn(v0);
                        __half h1 = __float2half_rn(v1);
                        g_vh16[base]         = h0;
                        g_vl16[base]         = __float2half_rn(v0 - __half2float(h0));
                        g_vh16[base + N_SEQ] = h1;
                        g_vl16[base + N_SEQ] = __float2half_rn(v1 - __half2float(h1));
                    } else {
                        float* outp = (z == 0) ? g_qs : g_ks;
                        float2 vv = { v0, v1 };
                        *(float2*)(outp + (((size_t)(bb * H_NUM + h) * N_SEQ) + n) * HD + d) = vv;
                    }
                } else {
                    float2 vv = { v0, v1 };
                    *(float2*)(dlin + (size_t)m * C_DIM + col) = vv;
                }
            }
        }
    }
}

// ---------------------------------------------------------------------------
// Kernel 2: L2-normalize q/k rows (unchanged).
// ---------------------------------------------------------------------------
__global__ void __launch_bounds__(256) norm_kernel(const float* __restrict__ logit_scale)
{
    int wrow = (blockIdx.x * blockDim.x + threadIdx.x) >> 5;
    int lane = threadIdx.x & 31;
    const int rows_per_tensor = BH * N_SEQ;
    if (wrow >= 2 * rows_per_tensor) return;
    int which = wrow >= rows_per_tensor;
    int row = wrow - which * rows_per_tensor;
    const float* ptr = (which ? g_ks : g_qs) + (size_t)row * HD;

    float x0 = ptr[2 * lane];
    float x1 = ptr[2 * lane + 1];
    float ss = x0 * x0 + x1 * x1;
#pragma unroll
    for (int o = 16; o > 0; o >>= 1) ss += __shfl_xor_sync(0xffffffffu, ss, o);
    float scale = 1.0f / fmaxf(sqrtf(ss), 1e-12f);
    if (!which) {
        int h = (row >> 10) & 15;
        scale *= expf(fminf(logit_scale[h], LOGMAX)) * LOG2E;
    }
    uint32_t hw, lw;
    split2(x0 * scale, x1 * scale, hw, lw);
    uint32_t* dh = which ? g_kh : g_qh;
    uint32_t* dl = which ? g_kl : g_ql;
    dh[(size_t)row * 32 + lane] = hw;
    dl[(size_t)row * 32 + lane] = lw;
}

// ---------------------------------------------------------------------------
// Kernel 3: tensor-core flash attention. QK = 3xbf16 (ldmatrix, term-major);
// PV = 2x fp16 MMAs: P packed fp16 straight from fp32 exp2 results,
// V pre-split fp16 hi/lo. cp.async K/V double buffer.
// ---------------------------------------------------------------------------
#define AW    36
#define Q_H   0
#define Q_L   (128 * AW)
#define KV_ST(s) (2 * 128 * AW + (s) * (4 * 64 * AW))
#define ATTN_SMEM_WORDS (2 * 128 * AW + 2 * 4 * 64 * AW)     // 27648 words
#define ATTN_SMEM_BYTES (ATTN_SMEM_WORDS * 4)                // 110592 bytes

__global__ void __launch_bounds__(256, 2) attn_kernel()
{
    extern __shared__ uint32_t sa[];
    const uint32_t sb = smem_u32(sa);

    const int bh = blockIdx.y;
    const int n0 = blockIdx.x * 128;
    const int tid  = threadIdx.x;
    const int warp = tid >> 5;
    const int lane = tid & 31;
    const int g    = lane >> 2;
    const int tig  = lane & 3;
    const int qr   = warp * 16;

    const size_t qrow0 = (size_t)bh * N_SEQ + n0;
    const size_t krow0 = (size_t)bh * N_SEQ;
    const size_t vrow0 = (size_t)bh * HD;
    const uint32_t* vwh = (const uint32_t*)g_vh16;
    const uint32_t* vwl = (const uint32_t*)g_vl16;

    // Stage Q (plain stores; first in-loop barrier publishes them)
#pragma unroll
    for (int u = 0; u < 4; u++) {
        int f = tid + 256 * u;
        int r = f >> 3, w4 = (f & 7) << 2;
        *(uint4*)&sa[Q_H + r * AW + w4] = *(const uint4*)&g_qh[(qrow0 + r) * 32 + w4];
        *(uint4*)&sa[Q_L + r * AW + w4] = *(const uint4*)&g_ql[(qrow0 + r) * 32 + w4];
    }

#define ISSUE_KV(kt) {                                                          \
        int _s = (kt) & 1;                                                      \
        uint32_t stb = sb + (uint32_t)KV_ST(_s) * 4;                            \
        _Pragma("unroll")                                                       \
        for (int u = 0; u < 2; u++) {                                           \
            int f = tid + 256 * u;                                              \
            int r = f >> 3, w4 = (f & 7) << 2;                                  \
            uint32_t dst = stb + (uint32_t)(r * AW + w4) * 4;                   \
            CP_ASYNC16(dst,                   &g_kh[(krow0 + (kt) * 64 + r) * 32 + w4]); \
            CP_ASYNC16(dst + 64 * AW * 4,     &g_kl[(krow0 + (kt) * 64 + r) * 32 + w4]); \
            CP_ASYNC16(dst + 2 * 64 * AW * 4, &vwh[(vrow0 + r) * 512 + (kt) * 32 + w4]); \
            CP_ASYNC16(dst + 3 * 64 * AW * 4, &vwl[(vrow0 + r) * 512 + (kt) * 32 + w4]); \
        }                                                                       \
        CP_COMMIT();                                                            \
    }

    // ldmatrix lane-address components (proven GEMM maps)
    const int arow_l = (lane & 7) + ((lane >> 3) & 1) * 8;
    const int awrd_l = (lane >> 4) * 4;
    const uint32_t qoff = (uint32_t)(((qr + arow_l) * AW + awrd_l) * 4);
    const int brow_l = ((lane >> 4) * 8) + (lane & 7);
    const int bwrd_l = ((lane >> 3) & 1) * 4;
    uint32_t kvoff[4];
#pragma unroll
    for (int p = 0; p < 4; p++)
        kvoff[p] = (uint32_t)(((p * 16 + brow_l) * AW + bwrd_l) * 4);

    const uint32_t sbQ_H = sb + (uint32_t)Q_H * 4;
    const uint32_t sbQ_L = sb + (uint32_t)Q_L * 4;

    float m0 = -1e30f, m1 = -1e30f, l0 = 0.f, l1 = 0.f;
    float o_acc[8][4];
#pragma unroll
    for (int i = 0; i < 8; i++)
#pragma unroll
        for (int c = 0; c < 4; c++) o_acc[i][c] = 0.f;

    ISSUE_KV(0);

    for (int kt = 0; kt < N_SEQ / 64; kt++) {
        CP_WAIT0();
        __syncthreads();
        if (kt + 1 < N_SEQ / 64) ISSUE_KV(kt + 1);

        const uint32_t stB  = sb + (uint32_t)KV_ST(kt & 1) * 4;
        const uint32_t bK_H = stB;
        const uint32_t bK_L = stB + 64 * AW * 4;
        const uint32_t bV_H = stB + 2 * 64 * AW * 4;
        const uint32_t bV_L = stB + 3 * 64 * AW * 4;

        // ---- S = Q K^T, 3xbf16, ldmatrix + term-major ----
        float s_acc[8][4];
#pragma unroll
        for (int i = 0; i < 8; i++)
#pragma unroll
            for (int c = 0; c < 4; c++) s_acc[i][c] = 0.f;

#pragma unroll
        for (int s = 0; s < 4; s++) {
            const uint32_t kb = (uint32_t)(s * 32);

            uint32_t qh[4], ql[4];
            ldsm_x4(qh, sbQ_H + qoff + kb);
            ldsm_x4(ql, sbQ_L + qoff + kb);

            uint32_t kh[4][4], kl[4][4];
#pragma unroll
            for (int p = 0; p < 4; p++) {
                ldsm_x4(kh[p], bK_H + kvoff[p] + kb);
                ldsm_x4(kl[p], bK_L + kvoff[p] + kb);
            }

#pragma unroll
            for (int nt = 0; nt < 8; nt++) {
                const int p = nt >> 1, e = (nt & 1) * 2;
                mma_bf16(s_acc[nt], qh, kh[p][e], kh[p][e + 1]);
            }
#pragma unroll
            for (int nt = 0; nt < 8; nt++) {
                const int p = nt >> 1, e = (nt & 1) * 2;
                mma_bf16(s_acc[nt], qh, kl[p][e], kl[p][e + 1]);
            }
#pragma unroll
            for (int nt = 0; nt < 8; nt++) {
                const int p = nt >> 1, e = (nt & 1) * 2;
                mma_bf16(s_acc[nt], ql, kh[p][e], kh[p][e + 1]);
            }
        }

        // ---- online softmax (base-2; exp in fp32) ----
        float rmax0 = -1e30f, rmax1 = -1e30f;
#pragma unroll
        for (int nt = 0; nt < 8; nt++) {
            rmax0 = fmaxf(rmax0, fmaxf(s_acc[nt][0], s_acc[nt][1]));
            rmax1 = fmaxf(rmax1, fmaxf(s_acc[nt][2], s_acc[nt][3]));
        }
        rmax0 = fmaxf(rmax0, __shfl_xor_sync(0xffffffffu, rmax0, 1));
        rmax0 = fmaxf(rmax0, __shfl_xor_sync(0xffffffffu, rmax0, 2));
        rmax1 = fmaxf(rmax1, __shfl_xor_sync(0xffffffffu, rmax1, 1));
        rmax1 = fmaxf(rmax1, __shfl_xor_sync(0xffffffffu, rmax1, 2));
        float mn0 = fmaxf(m0, rmax0), mn1 = fmaxf(m1, rmax1);
        float corr0 = fast_exp2(m0 - mn0), corr1 = fast_exp2(m1 - mn1);
        float rs0 = 0.f, rs1 = 0.f;
#pragma unroll
        for (int nt = 0; nt < 8; nt++) {
            s_acc[nt][0] = fast_exp2(s_acc[nt][0] - mn0);
            s_acc[nt][1] = fast_exp2(s_acc[nt][1] - mn0);
            s_acc[nt][2] = fast_exp2(s_acc[nt][2] - mn1);
            s_acc[nt][3] = fast_exp2(s_acc[nt][3] - mn1);
            rs0 += s_acc[nt][0] + s_acc[nt][1];
            rs1 += s_acc[nt][2] + s_acc[nt][3];
        }
        rs0 += __shfl_xor_sync(0xffffffffu, rs0, 1);
        rs0 += __shfl_xor_sync(0xffffffffu, rs0, 2);
        rs1 += __shfl_xor_sync(0xffffffffu, rs1, 1);
        rs1 += __shfl_xor_sync(0xffffffffu, rs1, 2);
        l0 = l0 * corr0 + rs0;  m0 = mn0;
        l1 = l1 * corr1 + rs1;  m1 = mn1;
#pragma unroll
        for (int nt = 0; nt < 8; nt++) {
            o_acc[nt][0] *= corr0;  o_acc[nt][1] *= corr0;
            o_acc[nt][2] *= corr1;  o_acc[nt][3] *= corr1;
        }

        // ---- O += P V : P single fp16 (packed), V fp16 hi/lo -> 2 MMAs ----
#pragma unroll
        for (int s = 0; s < 4; s++) {
            // A-frag: a0=(row g, k0-7), a1=(row g+8, k0-7),
            //         a2=(row g, k8-15), a3=(row g+8, k8-15)
            uint32_t pA[4];
            pA[0] = pack_f16x2(s_acc[2 * s][1],     s_acc[2 * s][0]);
            pA[1] = pack_f16x2(s_acc[2 * s][3],     s_acc[2 * s][2]);
            pA[2] = pack_f16x2(s_acc[2 * s + 1][1], s_acc[2 * s + 1][0]);
            pA[3] = pack_f16x2(s_acc[2 * s + 1][3], s_acc[2 * s + 1][2]);
            const uint32_t kb = (uint32_t)(s * 32);

            uint32_t vh[4][4], vl[4][4];
#pragma unroll
            for (int p = 0; p < 4; p++) {
                ldsm_x4(vh[p], bV_H + kvoff[p] + kb);
                ldsm_x4(vl[p], bV_L + kvoff[p] + kb);
            }

#pragma unroll
            for (int nt = 0; nt < 8; nt++) {
                const int p = nt >> 1, e = (nt & 1) * 2;
                mma_f16(o_acc[nt], pA, vh[p][e], vh[p][e + 1]);
            }
#pragma unroll
            for (int nt = 0; nt < 8; nt++) {
                const int p = nt >> 1, e = (nt & 1) * 2;
                mma_f16(o_acc[nt], pA, vl[p][e], vl[p][e + 1]);
            }
        }
    }
#undef ISSUE_KV

    // Epilogue: out[q][d] = o/l, stored pre-split for the output projection
    const int bb = bh >> 4;
    const int h  = bh & 15;
    float inv0 = 1.0f / l0, inv1 = 1.0f / l1;
    int nq0 = n0 + qr + g;
    size_t row0 = ((size_t)nq0 * B_SZ + bb) * CW;
    size_t row1 = ((size_t)(nq0 + 8) * B_SZ + bb) * CW;
#pragma unroll
    for (int nt = 0; nt < 8; nt++) {
        int w = h * 32 + nt * 4 + tig;
        uint32_t hw, lw;
        split2(o_acc[nt][0] * inv0, o_acc[nt][1] * inv0, hw, lw);
        g_xh[row0 + w] = hw;  g_xl[row0 + w] = lw;
        split2(o_acc[nt][2] * inv1, o_acc[nt][3] * inv1, hw, lw);
        g_xh[row1 + w] = hw;  g_xl[row1 + w] = lw;
    }
}

// ---------------------------------------------------------------------------
extern "C" void kernel_launch(void* const* d_in, const int* in_sizes, int n_in,
                              void* d_out, int out_size)
{
    const float* q     = (const float*)d_in[0];
    const float* k     = (const float*)d_in[1];
    const float* v     = (const float*)d_in[2];
    const float* w_in  = (const float*)d_in[3];
    const float* b_in  = (const float*)d_in[4];
    const float* ls    = (const float*)d_in[5];
    const float* w_out = (const float*)d_in[6];
    const float* b_out = (const float*)d_in[7];
    float* out = (float*)d_out;

    cudaFuncSetAttribute(gemm_tc,
                         cudaFuncAttributeMaxDynamicSharedMemorySize,
                         GEMM_SMEM_BYTES);
    cudaFuncSetAttribute(attn_kernel,
                         cudaFuncAttributeMaxDynamicSharedMemorySize,
                         ATTN_SMEM_BYTES);

    split_all<<<NF4_TOTAL / 256, 256>>>(
        (const float4*)q, (const float4*)k, (const float4*)v,
        (const float4*)w_in, (const float4*)w_out);

    gemm_tc<<<dim3(C_DIM / 128, M_ROWS / 128, 3), 256, GEMM_SMEM_BYTES>>>(
        b_in, nullptr, 0);
    norm_kernel<<<(2 * BH * N_SEQ) / 8, 256>>>(ls);
    attn_kernel<<<dim3(N_SEQ / 128, BH), 256, ATTN_SMEM_BYTES>>>();
    gemm_tc<<<dim3(C_DIM / 128, M_ROWS / 128, 1), 256, GEMM_SMEM_BYTES>>>(
        b_out, out, 1);
}

// round 17
// speedup vs baseline: 1.9629x; 1.0578x over previous
#include <cuda_runtime.h>
#include <cuda_bf16.h>
#include <cuda_fp16.h>
#include <math.h>
#include <stdint.h>

// Problem constants
#define N_SEQ  1024
#define B_SZ   4
#define C_DIM  1024
#define H_NUM  16
#define HD     64
#define BH     64          // B*H
#define M_ROWS 4096        // N*B
#define CW     512         // 32-bit words per C_DIM row of packed 16-bit
#define LOGMAX 4.6051701859880913680f  // log(100)
#define LOG2E  1.4426950408889634f

// Scratch (static device arrays -- no allocations allowed)
__device__ float g_qs[BH * N_SEQ * HD];  // fp32 [bh][n][d] (pre-norm q)
__device__ float g_ks[BH * N_SEQ * HD];

// Pre-split packed words (2 x 16-bit per uint32)
__device__ __align__(16) uint32_t g_inh[3 * M_ROWS * CW];  // q,k,v inputs (bf16 hi)
__device__ __align__(16) uint32_t g_inl[3 * M_ROWS * CW];  // (bf16 lo)
__device__ __align__(16) uint32_t g_wih[3 * 1024 * CW];    // in_proj_w (bf16 hi/lo)
__device__ __align__(16) uint32_t g_wil[3 * 1024 * CW];
__device__ __align__(16) uint32_t g_woh[1024 * CW];        // out_w (FP16 hi/lo)
__device__ __align__(16) uint32_t g_wol[1024 * CW];
__device__ __align__(16) uint32_t g_xh[M_ROWS * CW];       // attn out, single FP16 plane

// Attention operands (q/k packed bf16 hi/lo; V transposed fp16 hi/lo)
__device__ __align__(16) uint32_t g_qh[BH * N_SEQ * 32];   // [bh][n][dword]
__device__ __align__(16) uint32_t g_ql[BH * N_SEQ * 32];
__device__ __align__(16) uint32_t g_kh[BH * N_SEQ * 32];
__device__ __align__(16) uint32_t g_kl[BH * N_SEQ * 32];
__device__ __align__(16) __half g_vh16[BH * HD * N_SEQ];   // [bh][d][n] V^T hi
__device__ __align__(16) __half g_vl16[BH * HD * N_SEQ];   // lo

// ---------------------------------------------------------------------------
// Helpers (plain-target PTX only)
// ---------------------------------------------------------------------------
__device__ __forceinline__ uint32_t smem_u32(const void* p) {
    uint32_t a;
    asm("{ .reg .u64 t; cvta.to.shared.u64 t, %1; cvt.u32.u64 %0, t; }"
        : "=r"(a) : "l"(p));
    return a;
}

#define CP_ASYNC16(dst, src) \
    asm volatile("cp.async.cg.shared.global [%0], [%1], 16;" \
                 :: "r"(dst), "l"(src))
#define CP_COMMIT()  asm volatile("cp.async.commit_group;" ::: "memory")
#define CP_WAIT0()   asm volatile("cp.async.wait_group 0;" ::: "memory")

__device__ __forceinline__ void ldsm_x4(uint32_t* r, uint32_t addr) {
    asm volatile("ldmatrix.sync.aligned.m8n8.x4.shared.b16 {%0,%1,%2,%3}, [%4];"
                 : "=r"(r[0]), "=r"(r[1]), "=r"(r[2]), "=r"(r[3]) : "r"(addr));
}

__device__ __forceinline__ void mma_bf16(float* d, const uint32_t* a,
                                         uint32_t b0, uint32_t b1) {
    asm volatile(
        "mma.sync.aligned.m16n8k16.row.col.f32.bf16.bf16.f32 "
        "{%0,%1,%2,%3}, {%4,%5,%6,%7}, {%8,%9}, {%0,%1,%2,%3};"
        : "+f"(d[0]), "+f"(d[1]), "+f"(d[2]), "+f"(d[3])
        : "r"(a[0]), "r"(a[1]), "r"(a[2]), "r"(a[3]), "r"(b0), "r"(b1));
}

__device__ __forceinline__ void mma_f16(float* d, const uint32_t* a,
                                        uint32_t b0, uint32_t b1) {
    asm volatile(
        "mma.sync.aligned.m16n8k16.row.col.f32.f16.f16.f32 "
        "{%0,%1,%2,%3}, {%4,%5,%6,%7}, {%8,%9}, {%0,%1,%2,%3};"
        : "+f"(d[0]), "+f"(d[1]), "+f"(d[2]), "+f"(d[3])
        : "r"(a[0]), "r"(a[1]), "r"(a[2]), "r"(a[3]), "r"(b0), "r"(b1));
}

__device__ __forceinline__ uint32_t pack_bf2(float x, float y) {
    uint16_t lx = __bfloat16_as_ushort(__float2bfloat16_rn(x));
    uint16_t ly = __bfloat16_as_ushort(__float2bfloat16_rn(y));
    return (uint32_t)lx | ((uint32_t)ly << 16);
}

__device__ __forceinline__ void split2(float x, float y, uint32_t& hw, uint32_t& lw) {
    float hx = __bfloat162float(__float2bfloat16_rn(x));
    float hy = __bfloat162float(__float2bfloat16_rn(y));
    hw = pack_bf2(hx, hy);
    lw = pack_bf2(x - hx, y - hy);
}

// pack two fp32 -> f16x2 word: first operand -> HIGH half, second -> LOW half
__device__ __forceinline__ uint32_t pack_f16x2(float hi, float lo) {
    uint32_t r;
    asm("cvt.rn.f16x2.f32 %0, %1, %2;" : "=r"(r) : "f"(hi), "f"(lo));
    return r;
}

// fp16 split of a pair (x,y): hi word + lo word (element x -> LOW half)
__device__ __forceinline__ void split2_f16(float x, float y, uint32_t& hw, uint32_t& lw) {
    __half hx = __float2half_rn(x);
    __half hy = __float2half_rn(y);
    hw = pack_f16x2(__half2float(hy), __half2float(hx));   // y high, x low
    lw = pack_f16x2(y - __half2float(hy), x - __half2float(hx));
}

__device__ __forceinline__ float fast_exp2(float x) {
    float y;
    asm("ex2.approx.f32 %0, %1;" : "=f"(y) : "f"(x));
    return y;
}

// ---------------------------------------------------------------------------
// Kernel 0: merged split pre-pass, vectorized (2 float4 / thread, uint4 stores).
// Regions: [0,3*NI) q/k/v (bf16 split); [+NWI) in_proj_w (bf16); [+NWO) out_w (FP16).
// ---------------------------------------------------------------------------
#define NF4_IN (M_ROWS * C_DIM / 4)
#define NF4_WI (3 * 1024 * C_DIM / 4)
#define NF4_WO (1024 * C_DIM / 4)
#define NF4_TOTAL (3 * NF4_IN + NF4_WI + NF4_WO)

__global__ void __launch_bounds__(256) split_all(
    const float4* __restrict__ q, const float4* __restrict__ k,
    const float4* __restrict__ v, const float4* __restrict__ wi,
    const float4* __restrict__ wo)
{
    int i0 = (blockIdx.x * blockDim.x + threadIdx.x) * 2;   // float4 index, pair
    const float4* src;
    uint32_t *dh, *dl;
    int j;
    bool f16mode = false;
    if (i0 < 3 * NF4_IN) {
        int which = i0 / NF4_IN;
        j = i0 - which * NF4_IN;
        src = (which == 0) ? q : (which == 1) ? k : v;
        dh = g_inh + (size_t)which * M_ROWS * CW;
        dl = g_inl + (size_t)which * M_ROWS * CW;
    } else if (i0 < 3 * NF4_IN + NF4_WI) {
        j = i0 - 3 * NF4_IN;
        src = wi;  dh = g_wih;  dl = g_wil;
    } else {
        j = i0 - 3 * NF4_IN - NF4_WI;
        src = wo;  dh = g_woh;  dl = g_wol;
        f16mode = true;
    }
    float4 a = src[j], b = src[j + 1];
    uint4 hv, lv;
    if (f16mode) {
        split2_f16(a.x, a.y, hv.x, lv.x);
        split2_f16(a.z, a.w, hv.y, lv.y);
        split2_f16(b.x, b.y, hv.z, lv.z);
        split2_f16(b.z, b.w, hv.w, lv.w);
    } else {
        split2(a.x, a.y, hv.x, lv.x);
        split2(a.z, a.w, hv.y, lv.y);
        split2(b.x, b.y, hv.z, lv.z);
        split2(b.z, b.w, hv.w, lv.w);
    }
    *(uint4*)&dh[2 * (size_t)j] = hv;
    *(uint4*)&dl[2 * (size_t)j] = lv;
}

// ---------------------------------------------------------------------------
// Tensor-core GEMM, templated on MODE.
// MODE 0: 3xBF16 (PROVEN R13, bit-identical). q/k fp32 head scatter; v fp16^T.
// MODE 1: out-proj, A = g_xh single fp16 plane, B = out_w fp16 hi/lo,
//         2x mma.f16 (x*Wh + x*Wl). A-lo plane unused.
// ---------------------------------------------------------------------------
#define SW      20
#define PLANE_W (128 * SW)
#define STAGE_W (4 * PLANE_W)
#define GEMM_SMEM_BYTES (2 * STAGE_W * 4)   // 81920 bytes

template <int MODE>
__global__ void __launch_bounds__(256, 2) gemm_tc(
    const float* __restrict__ bias, float* __restrict__ dlin)
{
    extern __shared__ uint32_t sg[];
    const uint32_t sb = smem_u32(sg);

    const int z = blockIdx.z;
    const uint32_t* Agh = (MODE == 1) ? g_xh : g_inh + (size_t)z * M_ROWS * CW;
    const uint32_t* Agl = (MODE == 1) ? g_xh : g_inl + (size_t)z * M_ROWS * CW;
    const uint32_t* Bgh = (MODE == 1) ? g_woh : g_wih + (size_t)z * 1024 * CW;
    const uint32_t* Bgl = (MODE == 1) ? g_wol : g_wil + (size_t)z * 1024 * CW;
    const float* bp = bias + z * C_DIM;

    const int m0 = blockIdx.y * 128;
    const int n0 = blockIdx.x * 128;
    const int tid  = threadIdx.x;
    const int wid  = tid >> 5;
    const int lane = tid & 31;
    const int warp_m = wid >> 2;
    const int warp_n = wid & 3;

    float acc[4][4][4];
#pragma unroll
    for (int i = 0; i < 4; i++)
#pragma unroll
        for (int j = 0; j < 4; j++)
#pragma unroll
            for (int c = 0; c < 4; c++) acc[i][j][c] = 0.f;

    const int fr = tid >> 2;
    const int fc = (tid & 3) << 2;

#define ISSUE(kit) {                                                            \
        int _s = (kit) & 1;                                                     \
        int _kw = (kit) * 16;                                                   \
        _Pragma("unroll")                                                       \
        for (int u = 0; u < 2; u++) {                                           \
            int r = fr + 64 * u;                                                \
            uint32_t dst = sb + (uint32_t)(_s * STAGE_W + r * SW + fc) * 4;     \
            size_t ao = (size_t)(m0 + r) * CW + _kw + fc;                       \
            size_t bo = (size_t)(n0 + r) * CW + _kw + fc;                       \
            CP_ASYNC16(dst,                   Agh + ao);                        \
            if (MODE == 0) CP_ASYNC16(dst + PLANE_W * 4, Agl + ao);             \
            CP_ASYNC16(dst + 2 * PLANE_W * 4, Bgh + bo);                        \
            CP_ASYNC16(dst + 3 * PLANE_W * 4, Bgl + bo);                        \
        }                                                                       \
        CP_COMMIT();                                                            \
    }

    const int arow_l = (lane & 7) + ((lane >> 3) & 1) * 8;
    const int awrd_l = (lane >> 4) * 4;
    uint32_t aoff[4];
#pragma unroll
    for (int mt = 0; mt < 4; mt++)
        aoff[mt] = (uint32_t)(((warp_m * 64 + mt * 16 + arow_l) * SW + awrd_l) * 4);
    const int brow_l = ((lane >> 4) * 8) + (lane & 7);
    const int bwrd_l = ((lane >> 3) & 1) * 4;
    uint32_t boff[2];
#pragma unroll
    for (int p = 0; p < 2; p++)
        boff[p] = (uint32_t)(((warp_n * 32 + p * 16 + brow_l) * SW + bwrd_l) * 4);

    const int NIT = C_DIM / 32;   // 32

    ISSUE(0);

    for (int it = 0; it < NIT; it++) {
        CP_WAIT0();
        __syncthreads();
        if (it + 1 < NIT) ISSUE(it + 1);

        const int s = it & 1;
        const uint32_t bAh = sb + (uint32_t)(s * STAGE_W) * 4;
        const uint32_t bAl = bAh + PLANE_W * 4;
        const uint32_t bBh = bAh + 2 * PLANE_W * 4;
        const uint32_t bBl = bAh + 3 * PLANE_W * 4;

#pragma unroll
        for (int ks = 0; ks < 2; ks++) {
            const uint32_t kb = (uint32_t)(ks * 32);

            uint32_t bh[2][4], bl[2][4];
            ldsm_x4(bh[0], bBh + boff[0] + kb);
            ldsm_x4(bh[1], bBh + boff[1] + kb);
            ldsm_x4(bl[0], bBl + boff[0] + kb);
            ldsm_x4(bl[1], bBl + boff[1] + kb);

            uint32_t ah[4][4], al[4][4];
#pragma unroll
            for (int mt = 0; mt < 4; mt++) {
                ldsm_x4(ah[mt], bAh + aoff[mt] + kb);
                if (MODE == 0) ldsm_x4(al[mt], bAl + aoff[mt] + kb);
            }

            if (MODE == 0) {
#pragma unroll
                for (int mt = 0; mt < 4; mt++)
#pragma unroll
                    for (int n8 = 0; n8 < 4; n8++) {
                        const int p = n8 >> 1, e = (n8 & 1) * 2;
                        mma_bf16(acc[mt][n8], ah[mt], bh[p][e], bh[p][e + 1]);
                    }
#pragma unroll
                for (int mt = 0; mt < 4; mt++)
#pragma unroll
                    for (int n8 = 0; n8 < 4; n8++) {
                        const int p = n8 >> 1, e = (n8 & 1) * 2;
                        mma_bf16(acc[mt][n8], ah[mt], bl[p][e], bl[p][e + 1]);
                    }
#pragma unroll
                for (int mt = 0; mt < 4; mt++)
#pragma unroll
                    for (int n8 = 0; n8 < 4; n8++) {
                        const int p = n8 >> 1, e = (n8 & 1) * 2;
                        mma_bf16(acc[mt][n8], al[mt], bh[p][e], bh[p][e + 1]);
                    }
            } else {
#pragma unroll
                for (int mt = 0; mt < 4; mt++)
#pragma unroll
                    for (int n8 = 0; n8 < 4; n8++) {
                        const int p = n8 >> 1, e = (n8 & 1) * 2;
                        mma_f16(acc[mt][n8], ah[mt], bh[p][e], bh[p][e + 1]);
                    }
#pragma unroll
                for (int mt = 0; mt < 4; mt++)
#pragma unroll
                    for (int n8 = 0; n8 < 4; n8++) {
                        const int p = n8 >> 1, e = (n8 & 1) * 2;
                        mma_f16(acc[mt][n8], ah[mt], bl[p][e], bl[p][e + 1]);
                    }
            }
        }
    }
#undef ISSUE

    const int erow = lane >> 2;
    const int ecol = (lane & 3) * 2;
#pragma unroll
    for (int mt = 0; mt < 4; mt++) {
#pragma unroll
        for (int nt = 0; nt < 4; nt++) {
            int col = n0 + warp_n * 32 + nt * 8 + ecol;
            float bx = bp[col], by = bp[col + 1];
#pragma unroll
            for (int half = 0; half < 2; half++) {
                int m = m0 + warp_m * 64 + mt * 16 + erow + half * 8;
                float v0 = acc[mt][nt][half * 2 + 0] + bx;
                float v1 = acc[mt][nt][half * 2 + 1] + by;
                if (MODE == 0) {
                    int n = m >> 2, bb = m & 3;
                    int h = col >> 6, d = col & 63;
                    if (z == 2) {
                        size_t base = ((size_t)(bb * H_NUM + h) * HD + d) * N_SEQ + n;
                        __half h0 = __float2half_rn(v0);
                        __half h1 = __float2half_rn(v1);
                        g_vh16[base]         = h0;
                        g_vl16[base]         = __float2half_rn(v0 - __half2float(h0));
                        g_vh16[base + N_SEQ] = h1;
                        g_vl16[base + N_SEQ] = __float2half_rn(v1 - __half2float(h1));
                    } else {
                        float* outp = (z == 0) ? g_qs : g_ks;
                        float2 vv = { v0, v1 };
                        *(float2*)(outp + (((size_t)(bb * H_NUM + h) * N_SEQ) + n) * HD + d) = vv;
                    }
                } else {
                    float2 vv = { v0, v1 };
                    *(float2*)(dlin + (size_t)m * C_DIM + col) = vv;
                }
            }
        }
    }
}

// ---------------------------------------------------------------------------
// Kernel 2: L2-normalize q/k rows (unchanged).
// ---------------------------------------------------------------------------
__global__ void __launch_bounds__(256) norm_kernel(const float* __restrict__ logit_scale)
{
    int wrow = (blockIdx.x * blockDim.x + threadIdx.x) >> 5;
    int lane = threadIdx.x & 31;
    const int rows_per_tensor = BH * N_SEQ;
    if (wrow >= 2 * rows_per_tensor) return;
    int which = wrow >= rows_per_tensor;
    int row = wrow - which * rows_per_tensor;
    const float* ptr = (which ? g_ks : g_qs) + (size_t)row * HD;

    float x0 = ptr[2 * lane];
    float x1 = ptr[2 * lane + 1];
    float ss = x0 * x0 + x1 * x1;
#pragma unroll
    for (int o = 16; o > 0; o >>= 1) ss += __shfl_xor_sync(0xffffffffu, ss, o);
    float scale = 1.0f / fmaxf(sqrtf(ss), 1e-12f);
    if (!which) {
        int h = (row >> 10) & 15;
        scale *= expf(fminf(logit_scale[h], LOGMAX)) * LOG2E;
    }
    uint32_t hw, lw;
    split2(x0 * scale, x1 * scale, hw, lw);
    uint32_t* dh = which ? g_kh : g_qh;
    uint32_t* dl = which ? g_kl : g_ql;
    dh[(size_t)row * 32 + lane] = hw;
    dl[(size_t)row * 32 + lane] = lw;
}

// ---------------------------------------------------------------------------
// Kernel 3: tensor-core flash attention (R16 structure). Epilogue now emits
// a single fp16 plane g_xh for the fp16 out-projection.
// ---------------------------------------------------------------------------
#define AW    36
#define Q_H   0
#define Q_L   (128 * AW)
#define KV_ST(s) (2 * 128 * AW + (s) * (4 * 64 * AW))
#define ATTN_SMEM_WORDS (2 * 128 * AW + 2 * 4 * 64 * AW)     // 27648 words
#define ATTN_SMEM_BYTES (ATTN_SMEM_WORDS * 4)                // 110592 bytes

__global__ void __launch_bounds__(256, 2) attn_kernel()
{
    extern __shared__ uint32_t sa[];
    const uint32_t sb = smem_u32(sa);

    const int bh = blockIdx.y;
    const int n0 = blockIdx.x * 128;
    const int tid  = threadIdx.x;
    const int warp = tid >> 5;
    const int lane = tid & 31;
    const int g    = lane >> 2;
    const int tig  = lane & 3;
    const int qr   = warp * 16;

    const size_t qrow0 = (size_t)bh * N_SEQ + n0;
    const size_t krow0 = (size_t)bh * N_SEQ;
    const size_t vrow0 = (size_t)bh * HD;
    const uint32_t* vwh = (const uint32_t*)g_vh16;
    const uint32_t* vwl = (const uint32_t*)g_vl16;

#pragma unroll
    for (int u = 0; u < 4; u++) {
        int f = tid + 256 * u;
        int r = f >> 3, w4 = (f & 7) << 2;
        *(uint4*)&sa[Q_H + r * AW + w4] = *(const uint4*)&g_qh[(qrow0 + r) * 32 + w4];
        *(uint4*)&sa[Q_L + r * AW + w4] = *(const uint4*)&g_ql[(qrow0 + r) * 32 + w4];
    }

#define ISSUE_KV(kt) {                                                          \
        int _s = (kt) & 1;                                                      \
        uint32_t stb = sb + (uint32_t)KV_ST(_s) * 4;                            \
        _Pragma("unroll")                                                       \
        for (int u = 0; u < 2; u++) {                                           \
            int f = tid + 256 * u;                                              \
            int r = f >> 3, w4 = (f & 7) << 2;                                  \
            uint32_t dst = stb + (uint32_t)(r * AW + w4) * 4;                   \
            CP_ASYNC16(dst,                   &g_kh[(krow0 + (kt) * 64 + r) * 32 + w4]); \
            CP_ASYNC16(dst + 64 * AW * 4,     &g_kl[(krow0 + (kt) * 64 + r) * 32 + w4]); \
            CP_ASYNC16(dst + 2 * 64 * AW * 4, &vwh[(vrow0 + r) * 512 + (kt) * 32 + w4]); \
            CP_ASYNC16(dst + 3 * 64 * AW * 4, &vwl[(vrow0 + r) * 512 + (kt) * 32 + w4]); \
        }                                                                       \
        CP_COMMIT();                                                            \
    }

    const int arow_l = (lane & 7) + ((lane >> 3) & 1) * 8;
    const int awrd_l = (lane >> 4) * 4;
    const uint32_t qoff = (uint32_t)(((qr + arow_l) * AW + awrd_l) * 4);
    const int brow_l = ((lane >> 4) * 8) + (lane & 7);
    const int bwrd_l = ((lane >> 3) & 1) * 4;
    uint32_t kvoff[4];
#pragma unroll
    for (int p = 0; p < 4; p++)
        kvoff[p] = (uint32_t)(((p * 16 + brow_l) * AW + bwrd_l) * 4);

    const uint32_t sbQ_H = sb + (uint32_t)Q_H * 4;
    const uint32_t sbQ_L = sb + (uint32_t)Q_L * 4;

    float m0 = -1e30f, m1 = -1e30f, l0 = 0.f, l1 = 0.f;
    float o_acc[8][4];
#pragma unroll
    for (int i = 0; i < 8; i++)
#pragma unroll
        for (int c = 0; c < 4; c++) o_acc[i][c] = 0.f;

    ISSUE_KV(0);

    for (int kt = 0; kt < N_SEQ / 64; kt++) {
        CP_WAIT0();
        __syncthreads();
        if (kt + 1 < N_SEQ / 64) ISSUE_KV(kt + 1);

        const uint32_t stB  = sb + (uint32_t)KV_ST(kt & 1) * 4;
        const uint32_t bK_H = stB;
        const uint32_t bK_L = stB + 64 * AW * 4;
        const uint32_t bV_H = stB + 2 * 64 * AW * 4;
        const uint32_t bV_L = stB + 3 * 64 * AW * 4;

        float s_acc[8][4];
#pragma unroll
        for (int i = 0; i < 8; i++)
#pragma unroll
            for (int c = 0; c < 4; c++) s_acc[i][c] = 0.f;

#pragma unroll
        for (int s = 0; s < 4; s++) {
            const uint32_t kb = (uint32_t)(s * 32);

            uint32_t qh[4], ql[4];
            ldsm_x4(qh, sbQ_H + qoff + kb);
            ldsm_x4(ql, sbQ_L + qoff + kb);

            uint32_t kh[4][4], kl[4][4];
#pragma unroll
            for (int p = 0; p < 4; p++) {
                ldsm_x4(kh[p], bK_H + kvoff[p] + kb);
                ldsm_x4(kl[p], bK_L + kvoff[p] + kb);
            }

#pragma unroll
            for (int nt = 0; nt < 8; nt++) {
                const int p = nt >> 1, e = (nt & 1) * 2;
                mma_bf16(s_acc[nt], qh, kh[p][e], kh[p][e + 1]);
            }
#pragma unroll
            for (int nt = 0; nt < 8; nt++) {
                const int p = nt >> 1, e = (nt & 1) * 2;
                mma_bf16(s_acc[nt], qh, kl[p][e], kl[p][e + 1]);
            }
#pragma unroll
            for (int nt = 0; nt < 8; nt++) {
                const int p = nt >> 1, e = (nt & 1) * 2;
                mma_bf16(s_acc[nt], ql, kh[p][e], kh[p][e + 1]);
            }
        }

        float rmax0 = -1e30f, rmax1 = -1e30f;
#pragma unroll
        for (int nt = 0; nt < 8; nt++) {
            rmax0 = fmaxf(rmax0, fmaxf(s_acc[nt][0], s_acc[nt][1]));
            rmax1 = fmaxf(rmax1, fmaxf(s_acc[nt][2], s_acc[nt][3]));
        }
        rmax0 = fmaxf(rmax0, __shfl_xor_sync(0xffffffffu, rmax0, 1));
        rmax0 = fmaxf(rmax0, __shfl_xor_sync(0xffffffffu, rmax0, 2));
        rmax1 = fmaxf(rmax1, __shfl_xor_sync(0xffffffffu, rmax1, 1));
        rmax1 = fmaxf(rmax1, __shfl_xor_sync(0xffffffffu, rmax1, 2));
        float mn0 = fmaxf(m0, rmax0), mn1 = fmaxf(m1, rmax1);
        float corr0 = fast_exp2(m0 - mn0), corr1 = fast_exp2(m1 - mn1);
        float rs0 = 0.f, rs1 = 0.f;
#pragma unroll
        for (int nt = 0; nt < 8; nt++) {
            s_acc[nt][0] = fast_exp2(s_acc[nt][0] - mn0);
            s_acc[nt][1] = fast_exp2(s_acc[nt][1] - mn0);
            s_acc[nt][2] = fast_exp2(s_acc[nt][2] - mn1);
            s_acc[nt][3] = fast_exp2(s_acc[nt][3] - mn1);
            rs0 += s_acc[nt][0] + s_acc[nt][1];
            rs1 += s_acc[nt][2] + s_acc[nt][3];
        }
        rs0 += __shfl_xor_sync(0xffffffffu, rs0, 1);
        rs0 += __shfl_xor_sync(0xffffffffu, rs0, 2);
        rs1 += __shfl_xor_sync(0xffffffffu, rs1, 1);
        rs1 += __shfl_xor_sync(0xffffffffu, rs1, 2);
        l0 = l0 * corr0 + rs0;  m0 = mn0;
        l1 = l1 * corr1 + rs1;  m1 = mn1;
#pragma unroll
        for (int nt = 0; nt < 8; nt++) {
            o_acc[nt][0] *= corr0;  o_acc[nt][1] *= corr0;
            o_acc[nt][2] *= corr1;  o_acc[nt][3] *= corr1;
        }

#pragma unroll
        for (int s = 0; s < 4; s++) {
            uint32_t pA[4];
            pA[0] = pack_f16x2(s_acc[2 * s][1],     s_acc[2 * s][0]);
            pA[1] = pack_f16x2(s_acc[2 * s][3],     s_acc[2 * s][2]);
            pA[2] = pack_f16x2(s_acc[2 * s + 1][1], s_acc[2 * s + 1][0]);
            pA[3] = pack_f16x2(s_acc[2 * s + 1][3], s_acc[2 * s + 1][2]);
            const uint32_t kb = (uint32_t)(s * 32);

            uint32_t vh[4][4], vl[4][4];
#pragma unroll
            for (int p = 0; p < 4; p++) {
                ldsm_x4(vh[p], bV_H + kvoff[p] + kb);
                ldsm_x4(vl[p], bV_L + kvoff[p] + kb);
            }

#pragma unroll
            for (int nt = 0; nt < 8; nt++) {
                const int p = nt >> 1, e = (nt & 1) * 2;
                mma_f16(o_acc[nt], pA, vh[p][e], vh[p][e + 1]);
            }
#pragma unroll
            for (int nt = 0; nt < 8; nt++) {
                const int p = nt >> 1, e = (nt & 1) * 2;
                mma_f16(o_acc[nt], pA, vl[p][e], vl[p][e + 1]);
            }
        }
    }
#undef ISSUE_KV

    // Epilogue: out[q][d] = o/l as single fp16 plane (element 2w -> low half)
    const int bb = bh >> 4;
    const int h  = bh & 15;
    float inv0 = 1.0f / l0, inv1 = 1.0f / l1;
    int nq0 = n0 + qr + g;
    size_t row0 = ((size_t)nq0 * B_SZ + bb) * CW;
    size_t row1 = ((size_t)(nq0 + 8) * B_SZ + bb) * CW;
#pragma unroll
    for (int nt = 0; nt < 8; nt++) {
        int w = h * 32 + nt * 4 + tig;
        g_xh[row0 + w] = pack_f16x2(o_acc[nt][1] * inv0, o_acc[nt][0] * inv0);
        g_xh[row1 + w] = pack_f16x2(o_acc[nt][3] * inv1, o_acc[nt][2] * inv1);
    }
}

// ---------------------------------------------------------------------------
extern "C" void kernel_launch(void* const* d_in, const int* in_sizes, int n_in,
                              void* d_out, int out_size)
{
    const float* q     = (const float*)d_in[0];
    const float* k     = (const float*)d_in[1];
    const float* v     = (const float*)d_in[2];
    const float* w_in  = (const float*)d_in[3];
    const float* b_in  = (const float*)d_in[4];
    const float* ls    = (const float*)d_in[5];
    const float* w_out = (const float*)d_in[6];
    const float* b_out = (const float*)d_in[7];
    float* out = (float*)d_out;

    cudaFuncSetAttribute(gemm_tc<0>,
                         cudaFuncAttributeMaxDynamicSharedMemorySize,
                         GEMM_SMEM_BYTES);
    cudaFuncSetAttribute(gemm_tc<1>,
                         cudaFuncAttributeMaxDynamicSharedMemorySize,
                         GEMM_SMEM_BYTES);
    cudaFuncSetAttribute(attn_kernel,
                         cudaFuncAttributeMaxDynamicSharedMemorySize,
                         ATTN_SMEM_BYTES);

    split_all<<<NF4_TOTAL / 512, 256>>>(
        (const float4*)q, (const float4*)k, (const float4*)v,
        (const float4*)w_in, (const float4*)w_out);

    gemm_tc<0><<<dim3(C_DIM / 128, M_ROWS / 128, 3), 256, GEMM_SMEM_BYTES>>>(
        b_in, nullptr);
    norm_kernel<<<(2 * BH * N_SEQ) / 8, 256>>>(ls);
    attn_kernel<<<dim3(N_SEQ / 128, BH), 256, ATTN_SMEM_BYTES>>>();
    gemm_tc<1><<<dim3(C_DIM / 128, M_ROWS / 128, 1), 256, GEMM_SMEM_BYTES>>>(
        b_out, out);
}